// round 4
// baseline (speedup 1.0000x reference)
#include <cuda_runtime.h>
#include <math.h>

#define NBT   32768     // B*T
#define HID   1024
#define G3    768       // 3*OUT
#define OUTD  256
#define TST   128
#define INF   128
#define BATCH 256

typedef unsigned long long ull;

// ---------------- device-global scratch (no allocations allowed) -----------
__device__ __align__(16) float d_e[NBT * HID];     // leaky(embed) activations (raw)
__device__ __align__(16) float d_gi[NBT * G3];     // hoisted input gates (hx GRU)
__device__ __align__(16) float d_gim[TST * G3];    // input gates (hm GRU)
__device__ float d_sum[HID];
__device__ float d_sumsq[HID];
__device__ __align__(16) float d_scale[HID];
__device__ __align__(16) float d_shift[HID];
__device__ __align__(16) float d_wembT[INF * HID];   // W_emb^T  [k][n]
__device__ __align__(16) float d_wipT[HID * G3];     // (diag(scale)·w_ih_x)^T  [k][j]
__device__ __align__(16) float d_bip[G3];            // folded bias for gi
__device__ __align__(16) float d_whhT[OUTD * G3];    // w_hh_x^T [k][j]
__device__ __align__(16) float d_whhmT[OUTD * G3];   // w_hh_m^T [k][j]
__device__ __align__(16) float d_hxf[BATCH * OUTD];
__device__ __align__(16) float d_hmf[OUTD];

// ---------------- packed f32x2 helpers -------------------------------------
__device__ __forceinline__ ull pk2(float lo, float hi) {
    ull r; asm("mov.b64 %0,{%1,%2};" : "=l"(r) : "f"(lo), "f"(hi)); return r;
}
__device__ __forceinline__ void fma2(ull& d, ull a, ull b) {
    asm("fma.rn.f32x2 %0,%1,%2,%3;" : "=l"(d) : "l"(a), "l"(b), "l"(d));
}
__device__ __forceinline__ float2 upk2(ull v) {
    float2 f; asm("mov.b64 {%0,%1},%2;" : "=f"(f.x), "=f"(f.y) : "l"(v)); return f;
}

// ---------------- k_transpose: dst[c][r] = src[r][c] (* scale[c]) ----------
// R, C multiples of 32. use_scale multiplies by d_scale[c]. The use_scale==0
// instance (first launch) also zeroes the BN-stat accumulators.
__global__ void k_transpose(const float* __restrict__ src, float* __restrict__ dst,
                            int R, int C, int use_scale) {
    __shared__ float t[32][33];
    const int c0 = blockIdx.x * 32, r0 = blockIdx.y * 32;
    const int x = threadIdx.x, y0 = threadIdx.y;   // (32,8)
    if (!use_scale && blockIdx.x == 0 && blockIdx.y == 0) {
        for (int i = threadIdx.y * 32 + x; i < HID; i += 256) {
            d_sum[i] = 0.0f; d_sumsq[i] = 0.0f;
        }
    }
#pragma unroll
    for (int y = y0; y < 32; y += 8)
        t[y][x] = src[(size_t)(r0 + y) * C + c0 + x];
    __syncthreads();
#pragma unroll
    for (int y = y0; y < 32; y += 8) {
        float v = t[x][y];
        if (use_scale) v *= d_scale[c0 + y];
        dst[(size_t)(c0 + y) * R + r0 + x] = v;
    }
}

// ---------------- k_gemm: C[M x N] = A[M x K] @ BT[K x N] (+ epilogue) -----
// Tile 128x128, 256 threads, BK=16, register-prefetch double buffer,
// A pre-duplicated as f32x2 pairs in smem -> inner loop 6 LDS.128 + 32 FFMA2.
template<int KDIM, bool EMBED>
__global__ void __launch_bounds__(256)
k_gemm(const float* __restrict__ A, const float* __restrict__ BT,
       const float* __restrict__ bias, float* __restrict__ C, int Nld) {
    __shared__ __align__(16) ull As[16][130];     // duplicated (a,a) per element
    __shared__ __align__(16) float Bsf[16][136];
    const int m0 = blockIdx.x * 128, n0 = blockIdx.y * 128;
    const int tid = threadIdx.x, tx = tid & 15, ty = tid >> 4;

    const int ma0 = tid >> 2, qa = tid & 3, ma1 = ma0 + 64;
    const int kb0 = tid >> 5, cb = tid & 31, kb1 = kb0 + 8;

    ull acc[8][4];
#pragma unroll
    for (int i = 0; i < 8; i++) { acc[i][0] = 0; acc[i][1] = 0; acc[i][2] = 0; acc[i][3] = 0; }

    const float* pa0 = &A[(size_t)(m0 + ma0) * KDIM + qa * 4];
    const float* pa1 = &A[(size_t)(m0 + ma1) * KDIM + qa * 4];
    const float* pb0 = &BT[(size_t)kb0 * Nld + n0 + cb * 4];
    const float* pb1 = &BT[(size_t)kb1 * Nld + n0 + cb * 4];

    float4 ra0 = *(const float4*)pa0;
    float4 ra1 = *(const float4*)pa1;
    float4 rb0 = *(const float4*)pb0;
    float4 rb1 = *(const float4*)pb1;

    const int NC = KDIM / 16;
    for (int kt = 0; kt < NC; kt++) {
        // stage regs -> smem (A duplicated)
        As[qa * 4 + 0][ma0] = pk2(ra0.x, ra0.x); As[qa * 4 + 1][ma0] = pk2(ra0.y, ra0.y);
        As[qa * 4 + 2][ma0] = pk2(ra0.z, ra0.z); As[qa * 4 + 3][ma0] = pk2(ra0.w, ra0.w);
        As[qa * 4 + 0][ma1] = pk2(ra1.x, ra1.x); As[qa * 4 + 1][ma1] = pk2(ra1.y, ra1.y);
        As[qa * 4 + 2][ma1] = pk2(ra1.z, ra1.z); As[qa * 4 + 3][ma1] = pk2(ra1.w, ra1.w);
        *(float4*)&Bsf[kb0][cb * 4] = rb0;
        *(float4*)&Bsf[kb1][cb * 4] = rb1;
        __syncthreads();
        if (kt + 1 < NC) {
            const int ko = (kt + 1) * 16;
            ra0 = *(const float4*)(pa0 + ko);
            ra1 = *(const float4*)(pa1 + ko);
            rb0 = *(const float4*)(pb0 + (size_t)ko * Nld);
            rb1 = *(const float4*)(pb1 + (size_t)ko * Nld);
        }
#pragma unroll 4
        for (int k = 0; k < 16; k++) {
            ulonglong2 a01 = *(const ulonglong2*)&As[k][ty * 8];
            ulonglong2 a23 = *(const ulonglong2*)&As[k][ty * 8 + 2];
            ulonglong2 a45 = *(const ulonglong2*)&As[k][ty * 8 + 4];
            ulonglong2 a67 = *(const ulonglong2*)&As[k][ty * 8 + 6];
            ulonglong2 b01 = *(const ulonglong2*)&Bsf[k][tx * 8];
            ulonglong2 b23 = *(const ulonglong2*)&Bsf[k][tx * 8 + 4];
            fma2(acc[0][0], a01.x, b01.x); fma2(acc[0][1], a01.x, b01.y);
            fma2(acc[0][2], a01.x, b23.x); fma2(acc[0][3], a01.x, b23.y);
            fma2(acc[1][0], a01.y, b01.x); fma2(acc[1][1], a01.y, b01.y);
            fma2(acc[1][2], a01.y, b23.x); fma2(acc[1][3], a01.y, b23.y);
            fma2(acc[2][0], a23.x, b01.x); fma2(acc[2][1], a23.x, b01.y);
            fma2(acc[2][2], a23.x, b23.x); fma2(acc[2][3], a23.x, b23.y);
            fma2(acc[3][0], a23.y, b01.x); fma2(acc[3][1], a23.y, b01.y);
            fma2(acc[3][2], a23.y, b23.x); fma2(acc[3][3], a23.y, b23.y);
            fma2(acc[4][0], a45.x, b01.x); fma2(acc[4][1], a45.x, b01.y);
            fma2(acc[4][2], a45.x, b23.x); fma2(acc[4][3], a45.x, b23.y);
            fma2(acc[5][0], a45.y, b01.x); fma2(acc[5][1], a45.y, b01.y);
            fma2(acc[5][2], a45.y, b23.x); fma2(acc[5][3], a45.y, b23.y);
            fma2(acc[6][0], a67.x, b01.x); fma2(acc[6][1], a67.x, b01.y);
            fma2(acc[6][2], a67.x, b23.x); fma2(acc[6][3], a67.x, b23.y);
            fma2(acc[7][0], a67.y, b01.x); fma2(acc[7][1], a67.y, b01.y);
            fma2(acc[7][2], a67.y, b23.x); fma2(acc[7][3], a67.y, b23.y);
        }
        __syncthreads();
    }

    float bv[8];
#pragma unroll
    for (int c = 0; c < 8; c++) bv[c] = bias[n0 + tx * 8 + c];

    if (EMBED) {
        float ssum[8], ssq[8];
#pragma unroll
        for (int c = 0; c < 8; c++) { ssum[c] = 0.0f; ssq[c] = 0.0f; }
#pragma unroll
        for (int i = 0; i < 8; i++) {
            const int m = m0 + ty * 8 + i;
            float* er = &C[(size_t)m * Nld + n0 + tx * 8];
#pragma unroll
            for (int jj = 0; jj < 4; jj++) {
                float2 v = upk2(acc[i][jj]);
                const int c0 = jj * 2, c1 = jj * 2 + 1;
                float v0 = v.x + bv[c0]; v0 = (v0 >= 0.0f) ? v0 : 0.2f * v0;
                float v1 = v.y + bv[c1]; v1 = (v1 >= 0.0f) ? v1 : 0.2f * v1;
                er[c0] = v0; er[c1] = v1;
                ssum[c0] += v0; ssq[c0] += v0 * v0;
                ssum[c1] += v1; ssq[c1] += v1 * v1;
            }
        }
        float* sb = (float*)As;   // scratch reuse
        __syncthreads();
#pragma unroll
        for (int c = 0; c < 8; c++) sb[ty * 128 + tx * 8 + c] = ssum[c];
        __syncthreads();
        if (tid < 128) {
            float tot = 0.0f;
#pragma unroll
            for (int rr = 0; rr < 16; rr++) tot += sb[rr * 128 + tid];
            atomicAdd(&d_sum[n0 + tid], tot);
        }
        __syncthreads();
#pragma unroll
        for (int c = 0; c < 8; c++) sb[ty * 128 + tx * 8 + c] = ssq[c];
        __syncthreads();
        if (tid < 128) {
            float tot = 0.0f;
#pragma unroll
            for (int rr = 0; rr < 16; rr++) tot += sb[rr * 128 + tid];
            atomicAdd(&d_sumsq[n0 + tid], tot);
        }
    } else {
#pragma unroll
        for (int i = 0; i < 8; i++) {
            const int m = m0 + ty * 8 + i;
            float* gr = &C[(size_t)m * Nld + n0 + tx * 8];
#pragma unroll
            for (int jj = 0; jj < 4; jj++) {
                float2 v = upk2(acc[i][jj]);
                gr[jj * 2] = v.x + bv[jj * 2];
                gr[jj * 2 + 1] = v.y + bv[jj * 2 + 1];
            }
        }
    }
}

// ---------------- k_finalize: BN affine fold -------------------------------
__global__ void k_finalize(const float* __restrict__ gamma,
                           const float* __restrict__ beta) {
    const int h = threadIdx.x;  // 1024 threads, 1 block
    float mean = d_sum[h] * (1.0f / 32768.0f);
    float var = d_sumsq[h] * (1.0f / 32768.0f) - mean * mean;
    var = var > 0.0f ? var : 0.0f;
    float sc = gamma[h] * rsqrtf(var + 1e-5f);
    d_scale[h] = sc;
    d_shift[h] = beta[h] - mean * sc;
}

// ---------------- k_bprime: b'[j] = b_ih_x[j] + shift . w_ih_x[j,:] --------
__global__ void k_bprime(const float* __restrict__ w, const float* __restrict__ b) {
    const int j = blockIdx.x, t = threadIdx.x;   // 768 x 128
    float s = 0.0f;
    for (int h = t; h < HID; h += 128) s = fmaf(d_shift[h], w[(size_t)j * HID + h], s);
#pragma unroll
    for (int off = 16; off; off >>= 1) s += __shfl_xor_sync(0xFFFFFFFFu, s, off);
    __shared__ float red[4];
    if ((t & 31) == 0) red[t >> 5] = s;
    __syncthreads();
    if (t == 0) d_bip[j] = b[j] + red[0] + red[1] + red[2] + red[3];
}

// ---------------- k_trans: transpose both hidden-weight matrices -----------
__global__ void k_trans(const float* __restrict__ wx, const float* __restrict__ wm) {
    const int idx = blockIdx.x * 256 + threadIdx.x;  // G3*OUTD = 196608
    if (idx < G3 * OUTD) {
        const int j = idx / OUTD, k = idx % OUTD;
        d_whhT[k * G3 + j] = wx[idx];
        d_whhmT[k * G3 + j] = wm[idx];
    }
}

// ---------------- k_gim: gim[t][j] = mem[t]·w_ih_m[j] + b_ih_m[j] ----------
__global__ void k_gim(const float* __restrict__ mem, const float* __restrict__ wim,
                      const float* __restrict__ bim) {
    const int t = blockIdx.x, j = threadIdx.x;  // 128 x 768
    const float4* m4 = (const float4*)(mem + t * HID);
    const float4* w4 = (const float4*)(wim + (size_t)j * HID);
    float acc = bim[j];
#pragma unroll 4
    for (int k = 0; k < HID / 4; k++) {
        float4 a = m4[k], b = w4[k];
        acc = fmaf(a.x, b.x, fmaf(a.y, b.y, fmaf(a.z, b.z, fmaf(a.w, b.w, acc))));
    }
    d_gim[t * G3 + j] = acc;
}

// ---------------- k_scan: persistent GRU recurrences -----------------------
__global__ void __launch_bounds__(384, 1)
k_scan(const float* __restrict__ bhhx, const float* __restrict__ bhhm) {
    __shared__ ull hxd[4][OUTD];
    __shared__ float gh[4][G3];
    const int tid = threadIdx.x;
    const int j0 = 2 * tid;

    if (blockIdx.x < 64) {
        const int bb = blockIdx.x * 4;
        for (int i = tid; i < 4 * OUTD; i += 384) ((ull*)hxd)[i] = 0ull;
        const ull bh = *(const ull*)&bhhx[j0];
        __syncthreads();
        for (int t = 0; t < TST; t++) {
            ull a0 = bh, a1 = bh, a2 = bh, a3 = bh;
#pragma unroll 4
            for (int k = 0; k < OUTD; k++) {
                ull w = *(const ull*)&d_whhT[k * G3 + j0];
                fma2(a0, hxd[0][k], w); fma2(a1, hxd[1][k], w);
                fma2(a2, hxd[2][k], w); fma2(a3, hxd[3][k], w);
            }
            *(ull*)&gh[0][j0] = a0; *(ull*)&gh[1][j0] = a1;
            *(ull*)&gh[2][j0] = a2; *(ull*)&gh[3][j0] = a3;
            __syncthreads();
            if (tid < OUTD) {
#pragma unroll
                for (int b = 0; b < 4; b++) {
                    const float* gi = &d_gi[((size_t)(bb + b) * TST + t) * G3];
                    float hold = upk2(hxd[b][tid]).x;
                    float rr = 1.0f / (1.0f + expf(-(gi[tid] + gh[b][tid])));
                    float zz = 1.0f / (1.0f + expf(-(gi[OUTD + tid] + gh[b][OUTD + tid])));
                    float nn = tanhf(gi[2 * OUTD + tid] + rr * gh[b][2 * OUTD + tid]);
                    float hnew = (1.0f - zz) * nn + zz * hold;
                    hxd[b][tid] = pk2(hnew, hnew);
                }
            }
            __syncthreads();
        }
        if (tid < OUTD) {
#pragma unroll
            for (int b = 0; b < 4; b++)
                d_hxf[(bb + b) * OUTD + tid] = upk2(hxd[b][tid]).x;
        }
    } else {
        for (int i = tid; i < OUTD; i += 384) hxd[0][i] = 0ull;
        const ull bh = *(const ull*)&bhhm[j0];
        __syncthreads();
        for (int t = 0; t < TST; t++) {
            ull a0 = bh;
#pragma unroll 4
            for (int k = 0; k < OUTD; k++) {
                ull w = *(const ull*)&d_whhmT[k * G3 + j0];
                fma2(a0, hxd[0][k], w);
            }
            *(ull*)&gh[0][j0] = a0;
            __syncthreads();
            if (tid < OUTD) {
                const float* gi = &d_gim[t * G3];
                float hold = upk2(hxd[0][tid]).x;
                float rr = 1.0f / (1.0f + expf(-(gi[tid] + gh[0][tid])));
                float zz = 1.0f / (1.0f + expf(-(gi[OUTD + tid] + gh[0][OUTD + tid])));
                float nn = tanhf(gi[2 * OUTD + tid] + rr * gh[0][2 * OUTD + tid]);
                float hnew = (1.0f - zz) * nn + zz * hold;
                hxd[0][tid] = pk2(hnew, hnew);
            }
            __syncthreads();
        }
        if (tid < OUTD) d_hmf[tid] = upk2(hxd[0][tid]).x;
    }
}

// ---------------- k_final: cosine gate + blend -----------------------------
__global__ void k_final(const float* __restrict__ Wsx, const float* __restrict__ bsx,
                        const float* __restrict__ Wsm, const float* __restrict__ bsm,
                        float* __restrict__ out) {
    const int b = blockIdx.x, lane = threadIdx.x;  // 256 x 32
    float hx[8], hm[8];
#pragma unroll
    for (int i = 0; i < 8; i++) {
        hx[i] = d_hxf[b * OUTD + lane * 8 + i];
        hm[i] = d_hmf[lane * 8 + i];
    }
    float qx[4], qm[4];
#pragma unroll
    for (int s = 0; s < 4; s++) {
        float ax = 0.0f, am = 0.0f;
#pragma unroll
        for (int i = 0; i < 8; i++) {
            ax = fmaf(hx[i], Wsx[s * OUTD + lane * 8 + i], ax);
            am = fmaf(hm[i], Wsm[s * OUTD + lane * 8 + i], am);
        }
        for (int off = 16; off; off >>= 1) {
            ax += __shfl_xor_sync(0xFFFFFFFFu, ax, off);
            am += __shfl_xor_sync(0xFFFFFFFFu, am, off);
        }
        qx[s] = ax + bsx[s];
        qm[s] = am + bsm[s];
    }
    float num = 0.0f, nx = 0.0f, nm = 0.0f;
#pragma unroll
    for (int s = 0; s < 4; s++) {
        num = fmaf(qx[s], qm[s], num);
        nx = fmaf(qx[s], qx[s], nx);
        nm = fmaf(qm[s], qm[s], nm);
    }
    float den = fmaxf(sqrtf(nx), 1e-8f) * fmaxf(sqrtf(nm), 1e-8f);
    float g = 1.0f / (1.0f + expf(-num / den));
#pragma unroll
    for (int i = 0; i < 8; i++)
        out[b * OUTD + lane * 8 + i] = g * hx[i] + (1.0f - g) * hm[i];
}

// ---------------- launcher -------------------------------------------------
// Launch order puts k_gemm2 at position 6 so ncu (-s 5 -c 1) profiles it.
extern "C" void kernel_launch(void* const* d_in, const int* in_sizes, int n_in,
                              void* d_out, int out_size) {
    const float* x      = (const float*)d_in[0];
    const float* W_emb  = (const float*)d_in[1];
    const float* b_emb  = (const float*)d_in[2];
    const float* gamma  = (const float*)d_in[3];
    const float* beta   = (const float*)d_in[4];
    const float* memory = (const float*)d_in[5];
    const float* w_ih_x = (const float*)d_in[6];
    const float* w_hh_x = (const float*)d_in[7];
    const float* b_ih_x = (const float*)d_in[8];
    const float* b_hh_x = (const float*)d_in[9];
    const float* w_ih_m = (const float*)d_in[10];
    const float* w_hh_m = (const float*)d_in[11];
    const float* b_ih_m = (const float*)d_in[12];
    const float* b_hh_m = (const float*)d_in[13];
    const float* W_sx   = (const float*)d_in[14];
    const float* b_sx   = (const float*)d_in[15];
    const float* W_sm   = (const float*)d_in[16];
    const float* b_sm   = (const float*)d_in[17];
    float* out = (float*)d_out;

    float* wembT = nullptr; cudaGetSymbolAddress((void**)&wembT, d_wembT);
    float* wipT  = nullptr; cudaGetSymbolAddress((void**)&wipT,  d_wipT);
    float* ep    = nullptr; cudaGetSymbolAddress((void**)&ep,    d_e);
    float* gip   = nullptr; cudaGetSymbolAddress((void**)&gip,   d_gi);
    float* bip   = nullptr; cudaGetSymbolAddress((void**)&bip,   d_bip);

    // 1: transpose W_emb (also zeroes BN stat accumulators)
    k_transpose<<<dim3(4, 32), dim3(32, 8)>>>(W_emb, wembT, 1024, 128, 0);
    // 2: embed GEMM + leaky + BN stats
    k_gemm<INF, true><<<dim3(256, 8), 256>>>(x, wembT, b_emb, ep, HID);
    // 3: BN affine coefficients
    k_finalize<<<1, 1024>>>(gamma, beta);
    // 4: scaled transpose of w_ih_x
    k_transpose<<<dim3(32, 24), dim3(32, 8)>>>(w_ih_x, wipT, G3, HID, 1);
    // 5: folded bias
    k_bprime<<<768, 128>>>(w_ih_x, b_ih_x);
    // 6: the big gi GEMM  (profiled by ncu -s 5 -c 1)
    k_gemm<HID, false><<<dim3(256, 6), 256>>>(ep, wipT, bip, gip, G3);
    // 7-8: scan prep
    k_trans<<<768, 256>>>(w_hh_x, w_hh_m);
    k_gim<<<128, 768>>>(memory, w_ih_m, b_ih_m);
    // 9: recurrences
    k_scan<<<65, 384>>>(b_hh_x, b_hh_m);
    // 10: gate + blend
    k_final<<<256, 32>>>(W_sx, b_sx, W_sm, b_sm, out);
}

// round 5
// speedup vs baseline: 1.0813x; 1.0813x over previous
#include <cuda_runtime.h>
#include <math.h>

#define NBT   32768     // B*T
#define HID   1024
#define G3    768       // 3*OUT
#define OUTD  256
#define TST   128
#define INF   128
#define BATCH 256

typedef unsigned long long ull;

// ---------------- device-global scratch (no allocations allowed) -----------
__device__ __align__(16) float d_e[NBT * HID];     // leaky(embed) activations (raw)
__device__ __align__(16) float d_gi[NBT * G3];     // hoisted input gates (hx GRU)
__device__ __align__(16) float d_gim[TST * G3];    // input gates (hm GRU)
__device__ float d_sum[HID];
__device__ float d_sumsq[HID];
__device__ int   d_ctr;
__device__ __align__(16) float d_scale[HID];
__device__ __align__(16) float d_shift[HID];
__device__ __align__(16) float d_wembT[INF * HID];   // W_emb^T  [k][n]
__device__ __align__(16) float d_wipT[HID * G3];     // w_ih_x^T [k][j]
__device__ __align__(16) float d_whhT[OUTD * G3];    // w_hh_x^T [k][j]
__device__ __align__(16) float d_whhmT[OUTD * G3];   // w_hh_m^T [k][j]
__device__ __align__(16) float d_hxf[BATCH * OUTD];
__device__ __align__(16) float d_hmf[OUTD];

// ---------------- packed f32x2 helpers -------------------------------------
__device__ __forceinline__ ull pk2(float lo, float hi) {
    ull r; asm("mov.b64 %0,{%1,%2};" : "=l"(r) : "f"(lo), "f"(hi)); return r;
}
__device__ __forceinline__ void fma2(ull& d, ull a, ull b) {
    asm("fma.rn.f32x2 %0,%1,%2,%3;" : "=l"(d) : "l"(a), "l"(b), "l"(d));
}
__device__ __forceinline__ float2 upk2(ull v) {
    float2 f; asm("mov.b64 {%0,%1},%2;" : "=f"(f.x), "=f"(f.y) : "l"(v)); return f;
}

// ---------------- k_transpose: dst[c][r] = src[r][c] -----------------------
// grid (C/32, R/32), block (32,8). dozero: zero BN accumulators + counter.
__global__ void k_transpose(const float* __restrict__ src, float* __restrict__ dst,
                            int R, int C, int dozero) {
    __shared__ float t[32][33];
    const int c0 = blockIdx.x * 32, r0 = blockIdx.y * 32;
    const int x = threadIdx.x, y0 = threadIdx.y;
    if (dozero && blockIdx.x == 0 && blockIdx.y == 0) {
        for (int i = y0 * 32 + x; i < HID; i += 256) {
            d_sum[i] = 0.0f; d_sumsq[i] = 0.0f;
        }
        if (y0 == 0 && x == 0) d_ctr = 0;
    }
#pragma unroll
    for (int y = y0; y < 32; y += 8)
        t[y][x] = src[(size_t)(r0 + y) * C + c0 + x];
    __syncthreads();
#pragma unroll
    for (int y = y0; y < 32; y += 8)
        dst[(size_t)(c0 + y) * R + r0 + x] = t[x][y];
}

// ---------------- k_gemm: C[M x N] = A'[M x K] @ BT[K x N] (+ epilogue) ----
// Tile 128x128, 256 threads, BK=16, register-prefetch, A pre-duplicated as
// f32x2 pairs in smem. EMBED: +bias+leaky+BN-stats+fused finalize.
// !EMBED: A' = A*scale[k]+shift[k] (BN fold), +bias.
template<int KDIM, int EMBED>
__global__ void __launch_bounds__(256)
k_gemm(const float* __restrict__ A, const float* __restrict__ BT,
       const float* __restrict__ bias, float* __restrict__ C, int Nld,
       const float* __restrict__ gamma, const float* __restrict__ beta) {
    __shared__ __align__(16) ull As[16][130];
    __shared__ __align__(16) float Bsf[16][136];
    const int m0 = blockIdx.x * 128, n0 = blockIdx.y * 128;
    const int tid = threadIdx.x, tx = tid & 15, ty = tid >> 4;

    const int ma0 = tid >> 2, qa = tid & 3, ma1 = ma0 + 64;
    const int kb0 = tid >> 5, cb = tid & 31, kb1 = kb0 + 8;

    ull acc[8][4];
#pragma unroll
    for (int i = 0; i < 8; i++) { acc[i][0] = 0; acc[i][1] = 0; acc[i][2] = 0; acc[i][3] = 0; }

    const float* pa0 = &A[(size_t)(m0 + ma0) * KDIM + qa * 4];
    const float* pa1 = &A[(size_t)(m0 + ma1) * KDIM + qa * 4];
    const float* pb0 = &BT[(size_t)kb0 * Nld + n0 + cb * 4];
    const float* pb1 = &BT[(size_t)kb1 * Nld + n0 + cb * 4];

    float4 ra0 = *(const float4*)pa0;
    float4 ra1 = *(const float4*)pa1;
    float4 rb0 = *(const float4*)pb0;
    float4 rb1 = *(const float4*)pb1;

    const int NC = KDIM / 16;
    for (int kt = 0; kt < NC; kt++) {
        if (!EMBED) {  // BN affine fold on A
            const int kk = kt * 16 + qa * 4;
            float4 sc = *(const float4*)&d_scale[kk];
            float4 sh = *(const float4*)&d_shift[kk];
            ra0.x = fmaf(ra0.x, sc.x, sh.x); ra0.y = fmaf(ra0.y, sc.y, sh.y);
            ra0.z = fmaf(ra0.z, sc.z, sh.z); ra0.w = fmaf(ra0.w, sc.w, sh.w);
            ra1.x = fmaf(ra1.x, sc.x, sh.x); ra1.y = fmaf(ra1.y, sc.y, sh.y);
            ra1.z = fmaf(ra1.z, sc.z, sh.z); ra1.w = fmaf(ra1.w, sc.w, sh.w);
        }
        As[qa * 4 + 0][ma0] = pk2(ra0.x, ra0.x); As[qa * 4 + 1][ma0] = pk2(ra0.y, ra0.y);
        As[qa * 4 + 2][ma0] = pk2(ra0.z, ra0.z); As[qa * 4 + 3][ma0] = pk2(ra0.w, ra0.w);
        As[qa * 4 + 0][ma1] = pk2(ra1.x, ra1.x); As[qa * 4 + 1][ma1] = pk2(ra1.y, ra1.y);
        As[qa * 4 + 2][ma1] = pk2(ra1.z, ra1.z); As[qa * 4 + 3][ma1] = pk2(ra1.w, ra1.w);
        *(float4*)&Bsf[kb0][cb * 4] = rb0;
        *(float4*)&Bsf[kb1][cb * 4] = rb1;
        __syncthreads();
        if (kt + 1 < NC) {
            const int ko = (kt + 1) * 16;
            ra0 = *(const float4*)(pa0 + ko);
            ra1 = *(const float4*)(pa1 + ko);
            rb0 = *(const float4*)(pb0 + (size_t)ko * Nld);
            rb1 = *(const float4*)(pb1 + (size_t)ko * Nld);
        }
#pragma unroll 4
        for (int k = 0; k < 16; k++) {
            ulonglong2 a01 = *(const ulonglong2*)&As[k][ty * 8];
            ulonglong2 a23 = *(const ulonglong2*)&As[k][ty * 8 + 2];
            ulonglong2 a45 = *(const ulonglong2*)&As[k][ty * 8 + 4];
            ulonglong2 a67 = *(const ulonglong2*)&As[k][ty * 8 + 6];
            ulonglong2 b01 = *(const ulonglong2*)&Bsf[k][tx * 8];
            ulonglong2 b23 = *(const ulonglong2*)&Bsf[k][tx * 8 + 4];
            fma2(acc[0][0], a01.x, b01.x); fma2(acc[0][1], a01.x, b01.y);
            fma2(acc[0][2], a01.x, b23.x); fma2(acc[0][3], a01.x, b23.y);
            fma2(acc[1][0], a01.y, b01.x); fma2(acc[1][1], a01.y, b01.y);
            fma2(acc[1][2], a01.y, b23.x); fma2(acc[1][3], a01.y, b23.y);
            fma2(acc[2][0], a23.x, b01.x); fma2(acc[2][1], a23.x, b01.y);
            fma2(acc[2][2], a23.x, b23.x); fma2(acc[2][3], a23.x, b23.y);
            fma2(acc[3][0], a23.y, b01.x); fma2(acc[3][1], a23.y, b01.y);
            fma2(acc[3][2], a23.y, b23.x); fma2(acc[3][3], a23.y, b23.y);
            fma2(acc[4][0], a45.x, b01.x); fma2(acc[4][1], a45.x, b01.y);
            fma2(acc[4][2], a45.x, b23.x); fma2(acc[4][3], a45.x, b23.y);
            fma2(acc[5][0], a45.y, b01.x); fma2(acc[5][1], a45.y, b01.y);
            fma2(acc[5][2], a45.y, b23.x); fma2(acc[5][3], a45.y, b23.y);
            fma2(acc[6][0], a67.x, b01.x); fma2(acc[6][1], a67.x, b01.y);
            fma2(acc[6][2], a67.x, b23.x); fma2(acc[6][3], a67.x, b23.y);
            fma2(acc[7][0], a67.y, b01.x); fma2(acc[7][1], a67.y, b01.y);
            fma2(acc[7][2], a67.y, b23.x); fma2(acc[7][3], a67.y, b23.y);
        }
        __syncthreads();
    }

    float bv[8];
#pragma unroll
    for (int c = 0; c < 8; c++) bv[c] = bias[n0 + tx * 8 + c];

    if (EMBED) {
        float ssum[8], ssq[8];
#pragma unroll
        for (int c = 0; c < 8; c++) { ssum[c] = 0.0f; ssq[c] = 0.0f; }
#pragma unroll
        for (int i = 0; i < 8; i++) {
            const int m = m0 + ty * 8 + i;
            float* er = &C[(size_t)m * Nld + n0 + tx * 8];
#pragma unroll
            for (int jj = 0; jj < 4; jj++) {
                float2 v = upk2(acc[i][jj]);
                const int c0 = jj * 2, c1 = jj * 2 + 1;
                float v0 = v.x + bv[c0]; v0 = (v0 >= 0.0f) ? v0 : 0.2f * v0;
                float v1 = v.y + bv[c1]; v1 = (v1 >= 0.0f) ? v1 : 0.2f * v1;
                er[c0] = v0; er[c1] = v1;
                ssum[c0] += v0; ssq[c0] += v0 * v0;
                ssum[c1] += v1; ssq[c1] += v1 * v1;
            }
        }
        float* sb = (float*)As;
        __syncthreads();
#pragma unroll
        for (int c = 0; c < 8; c++) sb[ty * 128 + tx * 8 + c] = ssum[c];
        __syncthreads();
        if (tid < 128) {
            float tot = 0.0f;
#pragma unroll
            for (int rr = 0; rr < 16; rr++) tot += sb[rr * 128 + tid];
            atomicAdd(&d_sum[n0 + tid], tot);
        }
        __syncthreads();
#pragma unroll
        for (int c = 0; c < 8; c++) sb[ty * 128 + tx * 8 + c] = ssq[c];
        __syncthreads();
        if (tid < 128) {
            float tot = 0.0f;
#pragma unroll
            for (int rr = 0; rr < 16; rr++) tot += sb[rr * 128 + tid];
            atomicAdd(&d_sumsq[n0 + tid], tot);
        }
        // fused BN-finalize: last CTA computes scale/shift
        __threadfence();
        __syncthreads();
        __shared__ int last;
        if (tid == 0) {
            int v = atomicAdd(&d_ctr, 1);
            last = (v == (int)(gridDim.x * gridDim.y) - 1);
        }
        __syncthreads();
        if (last) {
            __threadfence();
            for (int h = tid; h < HID; h += 256) {
                float mean = d_sum[h] * (1.0f / 32768.0f);
                float var = d_sumsq[h] * (1.0f / 32768.0f) - mean * mean;
                var = var > 0.0f ? var : 0.0f;
                float sc = gamma[h] * rsqrtf(var + 1e-5f);
                d_scale[h] = sc;
                d_shift[h] = beta[h] - mean * sc;
            }
        }
    } else {
#pragma unroll
        for (int i = 0; i < 8; i++) {
            const int m = m0 + ty * 8 + i;
            float* gr = &C[(size_t)m * Nld + n0 + tx * 8];
#pragma unroll
            for (int jj = 0; jj < 4; jj++) {
                float2 v = upk2(acc[i][jj]);
                gr[jj * 2] = v.x + bv[jj * 2];
                gr[jj * 2 + 1] = v.y + bv[jj * 2 + 1];
            }
        }
    }
}

// ---------------- k_trans: transpose both hidden-weight matrices -----------
__global__ void k_trans(const float* __restrict__ wx, const float* __restrict__ wm) {
    const int idx = blockIdx.x * 256 + threadIdx.x;  // G3*OUTD
    if (idx < G3 * OUTD) {
        const int j = idx / OUTD, k = idx % OUTD;
        d_whhT[k * G3 + j] = wx[idx];
        d_whhmT[k * G3 + j] = wm[idx];
    }
}

// ---------------- k_gim: gim[t][j] = mem[t]·w_ih_m[j] + b_ih_m[j] ----------
__global__ void k_gim(const float* __restrict__ mem, const float* __restrict__ wim,
                      const float* __restrict__ bim) {
    const int t = blockIdx.x, j = threadIdx.x;  // 128 x 768
    const float4* m4 = (const float4*)(mem + t * HID);
    const float4* w4 = (const float4*)(wim + (size_t)j * HID);
    float acc = bim[j];
#pragma unroll 8
    for (int k = 0; k < HID / 4; k++) {
        float4 a = m4[k], b = w4[k];
        acc = fmaf(a.x, b.x, fmaf(a.y, b.y, fmaf(a.z, b.z, fmaf(a.w, b.w, acc))));
    }
    d_gim[t * G3 + j] = acc;
}

// ---------------- k_scan: persistent GRU recurrences -----------------------
// CTAs 0..63: hx for 4 batch rows each. CTA 64: the batch-invariant hm chain.
// unroll 16 -> ~16 outstanding LDG.64/warp so the L2 reads are BW- not
// latency-bound.
__global__ void __launch_bounds__(384, 1)
k_scan(const float* __restrict__ bhhx, const float* __restrict__ bhhm) {
    __shared__ ull hxd[4][OUTD];
    __shared__ float gh[4][G3];
    const int tid = threadIdx.x;
    const int j0 = 2 * tid;

    if (blockIdx.x < 64) {
        const int bb = blockIdx.x * 4;
        for (int i = tid; i < 4 * OUTD; i += 384) ((ull*)hxd)[i] = 0ull;
        const ull bh = *(const ull*)&bhhx[j0];
        __syncthreads();
        for (int t = 0; t < TST; t++) {
            ull a0 = bh, a1 = bh, a2 = bh, a3 = bh;
#pragma unroll 16
            for (int k = 0; k < OUTD; k++) {
                ull w = *(const ull*)&d_whhT[k * G3 + j0];
                fma2(a0, hxd[0][k], w); fma2(a1, hxd[1][k], w);
                fma2(a2, hxd[2][k], w); fma2(a3, hxd[3][k], w);
            }
            *(ull*)&gh[0][j0] = a0; *(ull*)&gh[1][j0] = a1;
            *(ull*)&gh[2][j0] = a2; *(ull*)&gh[3][j0] = a3;
            __syncthreads();
            if (tid < OUTD) {
#pragma unroll
                for (int b = 0; b < 4; b++) {
                    const float* gi = &d_gi[((size_t)(bb + b) * TST + t) * G3];
                    float hold = upk2(hxd[b][tid]).x;
                    float rr = 1.0f / (1.0f + expf(-(gi[tid] + gh[b][tid])));
                    float zz = 1.0f / (1.0f + expf(-(gi[OUTD + tid] + gh[b][OUTD + tid])));
                    float nn = tanhf(gi[2 * OUTD + tid] + rr * gh[b][2 * OUTD + tid]);
                    float hnew = (1.0f - zz) * nn + zz * hold;
                    hxd[b][tid] = pk2(hnew, hnew);
                }
            }
            __syncthreads();
        }
        if (tid < OUTD) {
#pragma unroll
            for (int b = 0; b < 4; b++)
                d_hxf[(bb + b) * OUTD + tid] = upk2(hxd[b][tid]).x;
        }
    } else {
        for (int i = tid; i < OUTD; i += 384) hxd[0][i] = 0ull;
        const ull bh = *(const ull*)&bhhm[j0];
        __syncthreads();
        for (int t = 0; t < TST; t++) {
            ull a0 = bh;
#pragma unroll 16
            for (int k = 0; k < OUTD; k++) {
                ull w = *(const ull*)&d_whhmT[k * G3 + j0];
                fma2(a0, hxd[0][k], w);
            }
            *(ull*)&gh[0][j0] = a0;
            __syncthreads();
            if (tid < OUTD) {
                const float* gi = &d_gim[t * G3];
                float hold = upk2(hxd[0][tid]).x;
                float rr = 1.0f / (1.0f + expf(-(gi[tid] + gh[0][tid])));
                float zz = 1.0f / (1.0f + expf(-(gi[OUTD + tid] + gh[0][OUTD + tid])));
                float nn = tanhf(gi[2 * OUTD + tid] + rr * gh[0][2 * OUTD + tid]);
                float hnew = (1.0f - zz) * nn + zz * hold;
                hxd[0][tid] = pk2(hnew, hnew);
            }
            __syncthreads();
        }
        if (tid < OUTD) d_hmf[tid] = upk2(hxd[0][tid]).x;
    }
}

// ---------------- k_final: cosine gate + blend -----------------------------
__global__ void k_final(const float* __restrict__ Wsx, const float* __restrict__ bsx,
                        const float* __restrict__ Wsm, const float* __restrict__ bsm,
                        float* __restrict__ out) {
    const int b = blockIdx.x, lane = threadIdx.x;  // 256 x 32
    float hx[8], hm[8];
#pragma unroll
    for (int i = 0; i < 8; i++) {
        hx[i] = d_hxf[b * OUTD + lane * 8 + i];
        hm[i] = d_hmf[lane * 8 + i];
    }
    float qx[4], qm[4];
#pragma unroll
    for (int s = 0; s < 4; s++) {
        float ax = 0.0f, am = 0.0f;
#pragma unroll
        for (int i = 0; i < 8; i++) {
            ax = fmaf(hx[i], Wsx[s * OUTD + lane * 8 + i], ax);
            am = fmaf(hm[i], Wsm[s * OUTD + lane * 8 + i], am);
        }
        for (int off = 16; off; off >>= 1) {
            ax += __shfl_xor_sync(0xFFFFFFFFu, ax, off);
            am += __shfl_xor_sync(0xFFFFFFFFu, am, off);
        }
        qx[s] = ax + bsx[s];
        qm[s] = am + bsm[s];
    }
    float num = 0.0f, nx = 0.0f, nm = 0.0f;
#pragma unroll
    for (int s = 0; s < 4; s++) {
        num = fmaf(qx[s], qm[s], num);
        nx = fmaf(qx[s], qx[s], nx);
        nm = fmaf(qm[s], qm[s], nm);
    }
    float den = fmaxf(sqrtf(nx), 1e-8f) * fmaxf(sqrtf(nm), 1e-8f);
    float g = 1.0f / (1.0f + expf(-num / den));
#pragma unroll
    for (int i = 0; i < 8; i++)
        out[b * OUTD + lane * 8 + i] = g * hx[i] + (1.0f - g) * hm[i];
}

// ---------------- launcher -------------------------------------------------
// Launch #4 = the big gi GEMM so ncu's profiled slot catches it.
extern "C" void kernel_launch(void* const* d_in, const int* in_sizes, int n_in,
                              void* d_out, int out_size) {
    const float* x      = (const float*)d_in[0];
    const float* W_emb  = (const float*)d_in[1];
    const float* b_emb  = (const float*)d_in[2];
    const float* gamma  = (const float*)d_in[3];
    const float* beta   = (const float*)d_in[4];
    const float* memory = (const float*)d_in[5];
    const float* w_ih_x = (const float*)d_in[6];
    const float* w_hh_x = (const float*)d_in[7];
    const float* b_ih_x = (const float*)d_in[8];
    const float* b_hh_x = (const float*)d_in[9];
    const float* w_ih_m = (const float*)d_in[10];
    const float* w_hh_m = (const float*)d_in[11];
    const float* b_ih_m = (const float*)d_in[12];
    const float* b_hh_m = (const float*)d_in[13];
    const float* W_sx   = (const float*)d_in[14];
    const float* b_sx   = (const float*)d_in[15];
    const float* W_sm   = (const float*)d_in[16];
    const float* b_sm   = (const float*)d_in[17];
    float* out = (float*)d_out;

    float* wembT = nullptr; cudaGetSymbolAddress((void**)&wembT, d_wembT);
    float* wipT  = nullptr; cudaGetSymbolAddress((void**)&wipT,  d_wipT);
    float* ep    = nullptr; cudaGetSymbolAddress((void**)&ep,    d_e);
    float* gip   = nullptr; cudaGetSymbolAddress((void**)&gip,   d_gi);

    // 1: plain transpose of w_ih_x (no deps)
    k_transpose<<<dim3(32, 24), dim3(32, 8)>>>(w_ih_x, wipT, G3, HID, 0);
    // 2: transpose W_emb + zero BN stat accumulators / counter
    k_transpose<<<dim3(4, 32), dim3(32, 8)>>>(W_emb, wembT, HID, INF, 1);
    // 3: embed GEMM + leaky + BN stats + fused finalize
    k_gemm<INF, 1><<<dim3(256, 8), 256>>>(x, wembT, b_emb, ep, HID, gamma, beta);
    // 4: the big gi GEMM with BN fold on A  (ncu-profiled slot)
    k_gemm<HID, 0><<<dim3(256, 6), 256>>>(ep, wipT, b_ih_x, gip, G3, nullptr, nullptr);
    // 5-6: scan prep
    k_trans<<<768, 256>>>(w_hh_x, w_hh_m);
    k_gim<<<128, 768>>>(memory, w_ih_m, b_ih_m);
    // 7: recurrences
    k_scan<<<65, 384>>>(b_hh_x, b_hh_m);
    // 8: gate + blend
    k_final<<<256, 32>>>(W_sx, b_sx, W_sm, b_sm, out);
}

// round 6
// speedup vs baseline: 1.3008x; 1.2029x over previous
#include <cuda_runtime.h>
#include <math.h>

#define NBT   32768     // B*T
#define HID   1024
#define G3    768       // 3*OUT
#define OUTD  256
#define TST   128
#define INF   128
#define BATCH 256

typedef unsigned long long ull;

// ---------------- device-global scratch (no allocations allowed) -----------
__device__ __align__(16) float d_e[NBT * HID];     // leaky(embed) activations (raw)
__device__ __align__(16) float d_gi[NBT * G3];     // hoisted input gates (hx GRU)
__device__ __align__(16) float d_gim[TST * G3];    // input gates (hm GRU)
__device__ float d_sum[HID];
__device__ float d_sumsq[HID];
__device__ int   d_ctr;
__device__ __align__(16) float d_scale[HID];
__device__ __align__(16) float d_shift[HID];
__device__ __align__(16) float d_whhT[OUTD * G3];    // w_hh_x^T [k][j]
__device__ __align__(16) float d_whhmT[OUTD * G3];   // w_hh_m^T [k][j]
__device__ __align__(16) float d_hxf[BATCH * OUTD];
__device__ __align__(16) float d_hmf[OUTD];

// ---------------- packed f32x2 helpers -------------------------------------
__device__ __forceinline__ ull pk2(float lo, float hi) {
    ull r; asm("mov.b64 %0,{%1,%2};" : "=l"(r) : "f"(lo), "f"(hi)); return r;
}
__device__ __forceinline__ void fma2(ull& d, ull a, ull b) {
    asm("fma.rn.f32x2 %0,%1,%2,%3;" : "=l"(d) : "l"(a), "l"(b), "l"(d));
}
__device__ __forceinline__ float2 upk2(ull v) {
    float2 f; asm("mov.b64 {%0,%1},%2;" : "=f"(f.x), "=f"(f.y) : "l"(v)); return f;
}
__device__ __forceinline__ float fsig(float x) {       // sigmoid via MUFU exp
    return 1.0f / (1.0f + __expf(-x));
}
__device__ __forceinline__ float ftanh(float x) {      // tanh via MUFU exp
    return 2.0f / (1.0f + __expf(-2.0f * x)) - 1.0f;
}

// ---------------- k_prep: zero stats + whh transposes + gim ----------------
// blocks [0,768): transpose chunks; [768,896): gim rows; 896: zero stats.
__global__ void k_prep(const float* __restrict__ wx, const float* __restrict__ wm,
                       const float* __restrict__ mem, const float* __restrict__ wim,
                       const float* __restrict__ bim) {
    const int blk = blockIdx.x, tid = threadIdx.x;
    if (blk < 768) {
        const int idx = blk * 256 + tid;          // over G3*OUTD
        const int j = idx / OUTD, k = idx % OUTD;
        d_whhT[k * G3 + j] = wx[idx];
        d_whhmT[k * G3 + j] = wm[idx];
    } else if (blk < 896) {
        const int t = blk - 768;
        const float4* m4 = (const float4*)(mem + t * HID);
        for (int j = tid; j < G3; j += 256) {
            const float4* w4 = (const float4*)(wim + (size_t)j * HID);
            float acc = bim[j];
#pragma unroll 8
            for (int k = 0; k < HID / 4; k++) {
                float4 a = m4[k], b = w4[k];
                acc = fmaf(a.x, b.x, fmaf(a.y, b.y, fmaf(a.z, b.z, fmaf(a.w, b.w, acc))));
            }
            d_gim[t * G3 + j] = acc;
        }
    } else {
        for (int i = tid; i < HID; i += 256) { d_sum[i] = 0.0f; d_sumsq[i] = 0.0f; }
        if (tid == 0) d_ctr = 0;
    }
}

// ---------------- k_gemm: C[M x N] = A'[M x K] @ B[N x K] (+ epilogue) -----
// Tile 128x128, 256 threads, BK=16, register-prefetch double buffer.
// A and B stored plain f32 in smem; (a,a) duplication happens in registers.
// EMBED: +bias+leaky+BN-stats+fused finalize. !EMBED: A' = A*scale[k]+shift[k].
template<int KDIM, int EMBED>
__global__ void __launch_bounds__(256)
k_gemm(const float* __restrict__ A, const float* __restrict__ B,
       const float* __restrict__ bias, float* __restrict__ C, int Nld,
       const float* __restrict__ gamma, const float* __restrict__ beta) {
    __shared__ __align__(16) float As[16][132];
    __shared__ __align__(16) float Bs[16][132];
    const int m0 = blockIdx.x * 128, n0 = blockIdx.y * 128;
    const int tid = threadIdx.x, tx = tid & 15, ty = tid >> 4;

    const int r0 = tid >> 2, qa = tid & 3, r1 = r0 + 64;   // rows within tile

    ull acc[8][4];
#pragma unroll
    for (int i = 0; i < 8; i++) { acc[i][0] = 0; acc[i][1] = 0; acc[i][2] = 0; acc[i][3] = 0; }

    const float* pa0 = &A[(size_t)(m0 + r0) * KDIM + qa * 4];
    const float* pa1 = &A[(size_t)(m0 + r1) * KDIM + qa * 4];
    const float* pb0 = &B[(size_t)(n0 + r0) * KDIM + qa * 4];
    const float* pb1 = &B[(size_t)(n0 + r1) * KDIM + qa * 4];

    float4 ra0 = *(const float4*)pa0;
    float4 ra1 = *(const float4*)pa1;
    float4 rb0 = *(const float4*)pb0;
    float4 rb1 = *(const float4*)pb1;

    const int NC = KDIM / 16;
    for (int kt = 0; kt < NC; kt++) {
        if (!EMBED) {  // BN affine fold on A
            const int kk = kt * 16 + qa * 4;
            float4 sc = *(const float4*)&d_scale[kk];
            float4 sh = *(const float4*)&d_shift[kk];
            ra0.x = fmaf(ra0.x, sc.x, sh.x); ra0.y = fmaf(ra0.y, sc.y, sh.y);
            ra0.z = fmaf(ra0.z, sc.z, sh.z); ra0.w = fmaf(ra0.w, sc.w, sh.w);
            ra1.x = fmaf(ra1.x, sc.x, sh.x); ra1.y = fmaf(ra1.y, sc.y, sh.y);
            ra1.z = fmaf(ra1.z, sc.z, sh.z); ra1.w = fmaf(ra1.w, sc.w, sh.w);
        }
        As[qa * 4 + 0][r0] = ra0.x; As[qa * 4 + 1][r0] = ra0.y;
        As[qa * 4 + 2][r0] = ra0.z; As[qa * 4 + 3][r0] = ra0.w;
        As[qa * 4 + 0][r1] = ra1.x; As[qa * 4 + 1][r1] = ra1.y;
        As[qa * 4 + 2][r1] = ra1.z; As[qa * 4 + 3][r1] = ra1.w;
        Bs[qa * 4 + 0][r0] = rb0.x; Bs[qa * 4 + 1][r0] = rb0.y;
        Bs[qa * 4 + 2][r0] = rb0.z; Bs[qa * 4 + 3][r0] = rb0.w;
        Bs[qa * 4 + 0][r1] = rb1.x; Bs[qa * 4 + 1][r1] = rb1.y;
        Bs[qa * 4 + 2][r1] = rb1.z; Bs[qa * 4 + 3][r1] = rb1.w;
        __syncthreads();
        if (kt + 1 < NC) {
            const int ko = (kt + 1) * 16;
            ra0 = *(const float4*)(pa0 + ko);
            ra1 = *(const float4*)(pa1 + ko);
            rb0 = *(const float4*)(pb0 + ko);
            rb1 = *(const float4*)(pb1 + ko);
        }
#pragma unroll 4
        for (int k = 0; k < 16; k++) {
            float4 af0 = *(const float4*)&As[k][ty * 8];
            float4 af1 = *(const float4*)&As[k][ty * 8 + 4];
            ulonglong2 b01 = *(const ulonglong2*)&Bs[k][tx * 8];
            ulonglong2 b23 = *(const ulonglong2*)&Bs[k][tx * 8 + 4];
            ull ap;
            ap = pk2(af0.x, af0.x);
            fma2(acc[0][0], ap, b01.x); fma2(acc[0][1], ap, b01.y);
            fma2(acc[0][2], ap, b23.x); fma2(acc[0][3], ap, b23.y);
            ap = pk2(af0.y, af0.y);
            fma2(acc[1][0], ap, b01.x); fma2(acc[1][1], ap, b01.y);
            fma2(acc[1][2], ap, b23.x); fma2(acc[1][3], ap, b23.y);
            ap = pk2(af0.z, af0.z);
            fma2(acc[2][0], ap, b01.x); fma2(acc[2][1], ap, b01.y);
            fma2(acc[2][2], ap, b23.x); fma2(acc[2][3], ap, b23.y);
            ap = pk2(af0.w, af0.w);
            fma2(acc[3][0], ap, b01.x); fma2(acc[3][1], ap, b01.y);
            fma2(acc[3][2], ap, b23.x); fma2(acc[3][3], ap, b23.y);
            ap = pk2(af1.x, af1.x);
            fma2(acc[4][0], ap, b01.x); fma2(acc[4][1], ap, b01.y);
            fma2(acc[4][2], ap, b23.x); fma2(acc[4][3], ap, b23.y);
            ap = pk2(af1.y, af1.y);
            fma2(acc[5][0], ap, b01.x); fma2(acc[5][1], ap, b01.y);
            fma2(acc[5][2], ap, b23.x); fma2(acc[5][3], ap, b23.y);
            ap = pk2(af1.z, af1.z);
            fma2(acc[6][0], ap, b01.x); fma2(acc[6][1], ap, b01.y);
            fma2(acc[6][2], ap, b23.x); fma2(acc[6][3], ap, b23.y);
            ap = pk2(af1.w, af1.w);
            fma2(acc[7][0], ap, b01.x); fma2(acc[7][1], ap, b01.y);
            fma2(acc[7][2], ap, b23.x); fma2(acc[7][3], ap, b23.y);
        }
        __syncthreads();
    }

    float bv[8];
#pragma unroll
    for (int c = 0; c < 8; c++) bv[c] = bias[n0 + tx * 8 + c];

    if (EMBED) {
        float ssum[8], ssq[8];
#pragma unroll
        for (int c = 0; c < 8; c++) { ssum[c] = 0.0f; ssq[c] = 0.0f; }
#pragma unroll
        for (int i = 0; i < 8; i++) {
            const int m = m0 + ty * 8 + i;
            float* er = &C[(size_t)m * Nld + n0 + tx * 8];
#pragma unroll
            for (int jj = 0; jj < 4; jj++) {
                float2 v = upk2(acc[i][jj]);
                const int c0 = jj * 2, c1 = jj * 2 + 1;
                float v0 = v.x + bv[c0]; v0 = (v0 >= 0.0f) ? v0 : 0.2f * v0;
                float v1 = v.y + bv[c1]; v1 = (v1 >= 0.0f) ? v1 : 0.2f * v1;
                er[c0] = v0; er[c1] = v1;
                ssum[c0] += v0; ssq[c0] += v0 * v0;
                ssum[c1] += v1; ssq[c1] += v1 * v1;
            }
        }
        float* sb = (float*)As;
        __syncthreads();
#pragma unroll
        for (int c = 0; c < 8; c++) sb[ty * 128 + tx * 8 + c] = ssum[c];
        __syncthreads();
        if (tid < 128) {
            float tot = 0.0f;
#pragma unroll
            for (int rr = 0; rr < 16; rr++) tot += sb[rr * 128 + tid];
            atomicAdd(&d_sum[n0 + tid], tot);
        }
        __syncthreads();
#pragma unroll
        for (int c = 0; c < 8; c++) sb[ty * 128 + tx * 8 + c] = ssq[c];
        __syncthreads();
        if (tid < 128) {
            float tot = 0.0f;
#pragma unroll
            for (int rr = 0; rr < 16; rr++) tot += sb[rr * 128 + tid];
            atomicAdd(&d_sumsq[n0 + tid], tot);
        }
        // fused BN-finalize: last CTA computes scale/shift
        __threadfence();
        __syncthreads();
        __shared__ int last;
        if (tid == 0) {
            int v = atomicAdd(&d_ctr, 1);
            last = (v == (int)(gridDim.x * gridDim.y) - 1);
        }
        __syncthreads();
        if (last) {
            __threadfence();
            for (int h = tid; h < HID; h += 256) {
                float mean = d_sum[h] * (1.0f / 32768.0f);
                float var = d_sumsq[h] * (1.0f / 32768.0f) - mean * mean;
                var = var > 0.0f ? var : 0.0f;
                float sc = gamma[h] * rsqrtf(var + 1e-5f);
                d_scale[h] = sc;
                d_shift[h] = beta[h] - mean * sc;
            }
        }
    } else {
#pragma unroll
        for (int i = 0; i < 8; i++) {
            const int m = m0 + ty * 8 + i;
            float* gr = &C[(size_t)m * Nld + n0 + tx * 8];
#pragma unroll
            for (int jj = 0; jj < 4; jj++) {
                float2 v = upk2(acc[i][jj]);
                gr[jj * 2] = v.x + bv[jj * 2];
                gr[jj * 2 + 1] = v.y + bv[jj * 2 + 1];
            }
        }
    }
}

// ---------------- k_scan: persistent GRU recurrences -----------------------
// CTAs 0..63: hx for 4 batch rows each. CTA 64: the batch-invariant hm chain.
// gi gate values are prefetched above the k-loop so their DRAM latency hides
// under ~6000 cycles of FFMA2 work.
__global__ void __launch_bounds__(384, 1)
k_scan(const float* __restrict__ bhhx, const float* __restrict__ bhhm) {
    __shared__ ull hxd[4][OUTD];
    __shared__ float gh[4][G3];
    const int tid = threadIdx.x;
    const int j0 = 2 * tid;

    if (blockIdx.x < 64) {
        const int bb = blockIdx.x * 4;
        for (int i = tid; i < 4 * OUTD; i += 384) ((ull*)hxd)[i] = 0ull;
        const ull bh = *(const ull*)&bhhx[j0];
        __syncthreads();
        for (int t = 0; t < TST; t++) {
            // prefetch gi gates for this step (independent of k-loop)
            float gr[4], gz[4], gn[4];
            if (tid < OUTD) {
#pragma unroll
                for (int b = 0; b < 4; b++) {
                    const float* gi = &d_gi[((size_t)(bb + b) * TST + t) * G3];
                    gr[b] = gi[tid]; gz[b] = gi[OUTD + tid]; gn[b] = gi[2 * OUTD + tid];
                }
            }
            ull a0 = bh, a1 = bh, a2 = bh, a3 = bh;
#pragma unroll 16
            for (int k = 0; k < OUTD; k++) {
                ull w = *(const ull*)&d_whhT[k * G3 + j0];
                fma2(a0, hxd[0][k], w); fma2(a1, hxd[1][k], w);
                fma2(a2, hxd[2][k], w); fma2(a3, hxd[3][k], w);
            }
            *(ull*)&gh[0][j0] = a0; *(ull*)&gh[1][j0] = a1;
            *(ull*)&gh[2][j0] = a2; *(ull*)&gh[3][j0] = a3;
            __syncthreads();
            if (tid < OUTD) {
#pragma unroll
                for (int b = 0; b < 4; b++) {
                    float hold = upk2(hxd[b][tid]).x;
                    float rr = fsig(gr[b] + gh[b][tid]);
                    float zz = fsig(gz[b] + gh[b][OUTD + tid]);
                    float nn = ftanh(gn[b] + rr * gh[b][2 * OUTD + tid]);
                    float hnew = (1.0f - zz) * nn + zz * hold;
                    hxd[b][tid] = pk2(hnew, hnew);
                }
            }
            __syncthreads();
        }
        if (tid < OUTD) {
#pragma unroll
            for (int b = 0; b < 4; b++)
                d_hxf[(bb + b) * OUTD + tid] = upk2(hxd[b][tid]).x;
        }
    } else {
        for (int i = tid; i < OUTD; i += 384) hxd[0][i] = 0ull;
        const ull bh = *(const ull*)&bhhm[j0];
        __syncthreads();
        for (int t = 0; t < TST; t++) {
            float gr0 = 0.0f, gz0 = 0.0f, gn0 = 0.0f;
            if (tid < OUTD) {
                const float* gi = &d_gim[t * G3];
                gr0 = gi[tid]; gz0 = gi[OUTD + tid]; gn0 = gi[2 * OUTD + tid];
            }
            ull a0 = bh;
#pragma unroll 16
            for (int k = 0; k < OUTD; k++) {
                ull w = *(const ull*)&d_whhmT[k * G3 + j0];
                fma2(a0, hxd[0][k], w);
            }
            *(ull*)&gh[0][j0] = a0;
            __syncthreads();
            if (tid < OUTD) {
                float hold = upk2(hxd[0][tid]).x;
                float rr = fsig(gr0 + gh[0][tid]);
                float zz = fsig(gz0 + gh[0][OUTD + tid]);
                float nn = ftanh(gn0 + rr * gh[0][2 * OUTD + tid]);
                float hnew = (1.0f - zz) * nn + zz * hold;
                hxd[0][tid] = pk2(hnew, hnew);
            }
            __syncthreads();
        }
        if (tid < OUTD) d_hmf[tid] = upk2(hxd[0][tid]).x;
    }
}

// ---------------- k_final: cosine gate + blend -----------------------------
__global__ void k_final(const float* __restrict__ Wsx, const float* __restrict__ bsx,
                        const float* __restrict__ Wsm, const float* __restrict__ bsm,
                        float* __restrict__ out) {
    const int b = blockIdx.x, lane = threadIdx.x;  // 256 x 32
    float hx[8], hm[8];
#pragma unroll
    for (int i = 0; i < 8; i++) {
        hx[i] = d_hxf[b * OUTD + lane * 8 + i];
        hm[i] = d_hmf[lane * 8 + i];
    }
    float qx[4], qm[4];
#pragma unroll
    for (int s = 0; s < 4; s++) {
        float ax = 0.0f, am = 0.0f;
#pragma unroll
        for (int i = 0; i < 8; i++) {
            ax = fmaf(hx[i], Wsx[s * OUTD + lane * 8 + i], ax);
            am = fmaf(hm[i], Wsm[s * OUTD + lane * 8 + i], am);
        }
        for (int off = 16; off; off >>= 1) {
            ax += __shfl_xor_sync(0xFFFFFFFFu, ax, off);
            am += __shfl_xor_sync(0xFFFFFFFFu, am, off);
        }
        qx[s] = ax + bsx[s];
        qm[s] = am + bsm[s];
    }
    float num = 0.0f, nx = 0.0f, nm = 0.0f;
#pragma unroll
    for (int s = 0; s < 4; s++) {
        num = fmaf(qx[s], qm[s], num);
        nx = fmaf(qx[s], qx[s], nx);
        nm = fmaf(qm[s], qm[s], nm);
    }
    float den = fmaxf(sqrtf(nx), 1e-8f) * fmaxf(sqrtf(nm), 1e-8f);
    float g = 1.0f / (1.0f + expf(-num / den));
#pragma unroll
    for (int i = 0; i < 8; i++)
        out[b * OUTD + lane * 8 + i] = g * hx[i] + (1.0f - g) * hm[i];
}

// ---------------- launcher -------------------------------------------------
// Launch #4 = k_scan so the ncu profiled slot catches it this round.
extern "C" void kernel_launch(void* const* d_in, const int* in_sizes, int n_in,
                              void* d_out, int out_size) {
    const float* x      = (const float*)d_in[0];
    const float* W_emb  = (const float*)d_in[1];
    const float* b_emb  = (const float*)d_in[2];
    const float* gamma  = (const float*)d_in[3];
    const float* beta   = (const float*)d_in[4];
    const float* memory = (const float*)d_in[5];
    const float* w_ih_x = (const float*)d_in[6];
    const float* w_hh_x = (const float*)d_in[7];
    const float* b_ih_x = (const float*)d_in[8];
    const float* b_hh_x = (const float*)d_in[9];
    const float* w_ih_m = (const float*)d_in[10];
    const float* w_hh_m = (const float*)d_in[11];
    const float* b_ih_m = (const float*)d_in[12];
    const float* b_hh_m = (const float*)d_in[13];
    const float* W_sx   = (const float*)d_in[14];
    const float* b_sx   = (const float*)d_in[15];
    const float* W_sm   = (const float*)d_in[16];
    const float* b_sm   = (const float*)d_in[17];
    float* out = (float*)d_out;

    float* ep  = nullptr; cudaGetSymbolAddress((void**)&ep,  d_e);
    float* gip = nullptr; cudaGetSymbolAddress((void**)&gip, d_gi);

    // 1: prep (zero stats + whh transposes + gim)
    k_prep<<<897, 256>>>(w_hh_x, w_hh_m, memory, w_ih_m, b_ih_m);
    // 2: embed GEMM + leaky + BN stats + fused finalize  (B = W_emb direct)
    k_gemm<INF, 1><<<dim3(256, 8), 256>>>(x, W_emb, b_emb, ep, HID, gamma, beta);
    // 3: big gi GEMM with BN fold on A  (B = w_ih_x direct)
    k_gemm<HID, 0><<<dim3(256, 6), 256>>>(ep, w_ih_x, b_ih_x, gip, G3, nullptr, nullptr);
    // 4: recurrences  (ncu-profiled slot)
    k_scan<<<65, 384>>>(b_hh_x, b_hh_m);
    // 5: gate + blend
    k_final<<<256, 32>>>(W_sx, b_sx, W_sm, b_sm, out);
}

// round 7
// speedup vs baseline: 1.4241x; 1.0948x over previous
#include <cuda_runtime.h>
#include <math.h>

#define NBT   32768     // B*T
#define HID   1024
#define G3    768       // 3*OUT
#define OUTD  256
#define TST   128
#define INF   128
#define BATCH 256

typedef unsigned long long ull;

// ---------------- device-global scratch (no allocations allowed) -----------
__device__ __align__(16) float d_e[NBT * HID];     // leaky(embed) activations (raw)
__device__ __align__(16) float d_gi[NBT * G3];     // hoisted input gates (hx GRU)
__device__ __align__(16) float d_gim[TST * G3];    // input gates (hm GRU)
__device__ float d_sum[HID];
__device__ float d_sumsq[HID];
__device__ int   d_ctr;
__device__ __align__(16) float d_scale[HID];
__device__ __align__(16) float d_shift[HID];
__device__ __align__(16) float d_whhT[OUTD * G3];    // w_hh_x^T [k][j]
__device__ __align__(16) float d_whhmT[OUTD * G3];   // w_hh_m^T [k][j]
__device__ __align__(16) float d_hxf[BATCH * OUTD];
__device__ __align__(16) float d_hmf[OUTD];

// ---------------- packed f32x2 helpers -------------------------------------
__device__ __forceinline__ ull pk2(float lo, float hi) {
    ull r; asm("mov.b64 %0,{%1,%2};" : "=l"(r) : "f"(lo), "f"(hi)); return r;
}
__device__ __forceinline__ void fma2(ull& d, ull a, ull b) {
    asm("fma.rn.f32x2 %0,%1,%2,%3;" : "=l"(d) : "l"(a), "l"(b), "l"(d));
}
__device__ __forceinline__ float2 upk2(ull v) {
    float2 f; asm("mov.b64 {%0,%1},%2;" : "=f"(f.x), "=f"(f.y) : "l"(v)); return f;
}
__device__ __forceinline__ float fsig(float x) {       // sigmoid via MUFU exp
    return 1.0f / (1.0f + __expf(-x));
}
__device__ __forceinline__ float ftanh(float x) {      // tanh via MUFU exp
    return 2.0f / (1.0f + __expf(-2.0f * x)) - 1.0f;
}

// ---------------- k_prep: zero stats + whh transposes + gim ----------------
// blocks [0,768): transpose chunks; [768,896): gim rows; 896: zero stats.
__global__ void k_prep(const float* __restrict__ wx, const float* __restrict__ wm,
                       const float* __restrict__ mem, const float* __restrict__ wim,
                       const float* __restrict__ bim) {
    const int blk = blockIdx.x, tid = threadIdx.x;
    if (blk < 768) {
        const int idx = blk * 256 + tid;          // over G3*OUTD
        const int j = idx / OUTD, k = idx % OUTD;
        d_whhT[k * G3 + j] = wx[idx];
        d_whhmT[k * G3 + j] = wm[idx];
    } else if (blk < 896) {
        const int t = blk - 768;
        const float4* m4 = (const float4*)(mem + t * HID);
        for (int j = tid; j < G3; j += 256) {
            const float4* w4 = (const float4*)(wim + (size_t)j * HID);
            float acc = bim[j];
#pragma unroll 8
            for (int k = 0; k < HID / 4; k++) {
                float4 a = m4[k], b = w4[k];
                acc = fmaf(a.x, b.x, fmaf(a.y, b.y, fmaf(a.z, b.z, fmaf(a.w, b.w, acc))));
            }
            d_gim[t * G3 + j] = acc;
        }
    } else {
        for (int i = tid; i < HID; i += 256) { d_sum[i] = 0.0f; d_sumsq[i] = 0.0f; }
        if (tid == 0) d_ctr = 0;
    }
}

// ---------------- k_gemm: C[M x N] = A'[M x K] @ B[N x K] (+ epilogue) -----
template<int KDIM, int EMBED>
__global__ void __launch_bounds__(256)
k_gemm(const float* __restrict__ A, const float* __restrict__ B,
       const float* __restrict__ bias, float* __restrict__ C, int Nld,
       const float* __restrict__ gamma, const float* __restrict__ beta) {
    __shared__ __align__(16) float As[16][132];
    __shared__ __align__(16) float Bs[16][132];
    const int m0 = blockIdx.x * 128, n0 = blockIdx.y * 128;
    const int tid = threadIdx.x, tx = tid & 15, ty = tid >> 4;

    const int r0 = tid >> 2, qa = tid & 3, r1 = r0 + 64;   // rows within tile

    ull acc[8][4];
#pragma unroll
    for (int i = 0; i < 8; i++) { acc[i][0] = 0; acc[i][1] = 0; acc[i][2] = 0; acc[i][3] = 0; }

    const float* pa0 = &A[(size_t)(m0 + r0) * KDIM + qa * 4];
    const float* pa1 = &A[(size_t)(m0 + r1) * KDIM + qa * 4];
    const float* pb0 = &B[(size_t)(n0 + r0) * KDIM + qa * 4];
    const float* pb1 = &B[(size_t)(n0 + r1) * KDIM + qa * 4];

    float4 ra0 = *(const float4*)pa0;
    float4 ra1 = *(const float4*)pa1;
    float4 rb0 = *(const float4*)pb0;
    float4 rb1 = *(const float4*)pb1;

    const int NC = KDIM / 16;
    for (int kt = 0; kt < NC; kt++) {
        if (!EMBED) {  // BN affine fold on A
            const int kk = kt * 16 + qa * 4;
            float4 sc = *(const float4*)&d_scale[kk];
            float4 sh = *(const float4*)&d_shift[kk];
            ra0.x = fmaf(ra0.x, sc.x, sh.x); ra0.y = fmaf(ra0.y, sc.y, sh.y);
            ra0.z = fmaf(ra0.z, sc.z, sh.z); ra0.w = fmaf(ra0.w, sc.w, sh.w);
            ra1.x = fmaf(ra1.x, sc.x, sh.x); ra1.y = fmaf(ra1.y, sc.y, sh.y);
            ra1.z = fmaf(ra1.z, sc.z, sh.z); ra1.w = fmaf(ra1.w, sc.w, sh.w);
        }
        As[qa * 4 + 0][r0] = ra0.x; As[qa * 4 + 1][r0] = ra0.y;
        As[qa * 4 + 2][r0] = ra0.z; As[qa * 4 + 3][r0] = ra0.w;
        As[qa * 4 + 0][r1] = ra1.x; As[qa * 4 + 1][r1] = ra1.y;
        As[qa * 4 + 2][r1] = ra1.z; As[qa * 4 + 3][r1] = ra1.w;
        Bs[qa * 4 + 0][r0] = rb0.x; Bs[qa * 4 + 1][r0] = rb0.y;
        Bs[qa * 4 + 2][r0] = rb0.z; Bs[qa * 4 + 3][r0] = rb0.w;
        Bs[qa * 4 + 0][r1] = rb1.x; Bs[qa * 4 + 1][r1] = rb1.y;
        Bs[qa * 4 + 2][r1] = rb1.z; Bs[qa * 4 + 3][r1] = rb1.w;
        __syncthreads();
        if (kt + 1 < NC) {
            const int ko = (kt + 1) * 16;
            ra0 = *(const float4*)(pa0 + ko);
            ra1 = *(const float4*)(pa1 + ko);
            rb0 = *(const float4*)(pb0 + ko);
            rb1 = *(const float4*)(pb1 + ko);
        }
#pragma unroll 4
        for (int k = 0; k < 16; k++) {
            float4 af0 = *(const float4*)&As[k][ty * 8];
            float4 af1 = *(const float4*)&As[k][ty * 8 + 4];
            ulonglong2 b01 = *(const ulonglong2*)&Bs[k][tx * 8];
            ulonglong2 b23 = *(const ulonglong2*)&Bs[k][tx * 8 + 4];
            ull ap;
            ap = pk2(af0.x, af0.x);
            fma2(acc[0][0], ap, b01.x); fma2(acc[0][1], ap, b01.y);
            fma2(acc[0][2], ap, b23.x); fma2(acc[0][3], ap, b23.y);
            ap = pk2(af0.y, af0.y);
            fma2(acc[1][0], ap, b01.x); fma2(acc[1][1], ap, b01.y);
            fma2(acc[1][2], ap, b23.x); fma2(acc[1][3], ap, b23.y);
            ap = pk2(af0.z, af0.z);
            fma2(acc[2][0], ap, b01.x); fma2(acc[2][1], ap, b01.y);
            fma2(acc[2][2], ap, b23.x); fma2(acc[2][3], ap, b23.y);
            ap = pk2(af0.w, af0.w);
            fma2(acc[3][0], ap, b01.x); fma2(acc[3][1], ap, b01.y);
            fma2(acc[3][2], ap, b23.x); fma2(acc[3][3], ap, b23.y);
            ap = pk2(af1.x, af1.x);
            fma2(acc[4][0], ap, b01.x); fma2(acc[4][1], ap, b01.y);
            fma2(acc[4][2], ap, b23.x); fma2(acc[4][3], ap, b23.y);
            ap = pk2(af1.y, af1.y);
            fma2(acc[5][0], ap, b01.x); fma2(acc[5][1], ap, b01.y);
            fma2(acc[5][2], ap, b23.x); fma2(acc[5][3], ap, b23.y);
            ap = pk2(af1.z, af1.z);
            fma2(acc[6][0], ap, b01.x); fma2(acc[6][1], ap, b01.y);
            fma2(acc[6][2], ap, b23.x); fma2(acc[6][3], ap, b23.y);
            ap = pk2(af1.w, af1.w);
            fma2(acc[7][0], ap, b01.x); fma2(acc[7][1], ap, b01.y);
            fma2(acc[7][2], ap, b23.x); fma2(acc[7][3], ap, b23.y);
        }
        __syncthreads();
    }

    float bv[8];
#pragma unroll
    for (int c = 0; c < 8; c++) bv[c] = bias[n0 + tx * 8 + c];

    if (EMBED) {
        float ssum[8], ssq[8];
#pragma unroll
        for (int c = 0; c < 8; c++) { ssum[c] = 0.0f; ssq[c] = 0.0f; }
#pragma unroll
        for (int i = 0; i < 8; i++) {
            const int m = m0 + ty * 8 + i;
            float* er = &C[(size_t)m * Nld + n0 + tx * 8];
#pragma unroll
            for (int jj = 0; jj < 4; jj++) {
                float2 v = upk2(acc[i][jj]);
                const int c0 = jj * 2, c1 = jj * 2 + 1;
                float v0 = v.x + bv[c0]; v0 = (v0 >= 0.0f) ? v0 : 0.2f * v0;
                float v1 = v.y + bv[c1]; v1 = (v1 >= 0.0f) ? v1 : 0.2f * v1;
                er[c0] = v0; er[c1] = v1;
                ssum[c0] += v0; ssq[c0] += v0 * v0;
                ssum[c1] += v1; ssq[c1] += v1 * v1;
            }
        }
        float* sb = (float*)As;
        __syncthreads();
#pragma unroll
        for (int c = 0; c < 8; c++) sb[ty * 128 + tx * 8 + c] = ssum[c];
        __syncthreads();
        if (tid < 128) {
            float tot = 0.0f;
#pragma unroll
            for (int rr = 0; rr < 16; rr++) tot += sb[rr * 128 + tid];
            atomicAdd(&d_sum[n0 + tid], tot);
        }
        __syncthreads();
#pragma unroll
        for (int c = 0; c < 8; c++) sb[ty * 128 + tx * 8 + c] = ssq[c];
        __syncthreads();
        if (tid < 128) {
            float tot = 0.0f;
#pragma unroll
            for (int rr = 0; rr < 16; rr++) tot += sb[rr * 128 + tid];
            atomicAdd(&d_sumsq[n0 + tid], tot);
        }
        // fused BN-finalize: last CTA computes scale/shift
        __threadfence();
        __syncthreads();
        __shared__ int last;
        if (tid == 0) {
            int v = atomicAdd(&d_ctr, 1);
            last = (v == (int)(gridDim.x * gridDim.y) - 1);
        }
        __syncthreads();
        if (last) {
            __threadfence();
            for (int h = tid; h < HID; h += 256) {
                float mean = d_sum[h] * (1.0f / 32768.0f);
                float var = d_sumsq[h] * (1.0f / 32768.0f) - mean * mean;
                var = var > 0.0f ? var : 0.0f;
                float sc = gamma[h] * rsqrtf(var + 1e-5f);
                d_scale[h] = sc;
                d_shift[h] = beta[h] - mean * sc;
            }
        }
    } else {
#pragma unroll
        for (int i = 0; i < 8; i++) {
            const int m = m0 + ty * 8 + i;
            float* gr = &C[(size_t)m * Nld + n0 + tx * 8];
#pragma unroll
            for (int jj = 0; jj < 4; jj++) {
                float2 v = upk2(acc[i][jj]);
                gr[jj * 2] = v.x + bv[jj * 2];
                gr[jj * 2 + 1] = v.y + bv[jj * 2 + 1];
            }
        }
    }
}

// ---------------- k_scan: persistent GRU recurrences (b-packed) ------------
// 192 threads. CTAs 0..63: hx for 4 batch rows (packed as 2 f32x2 b-pairs).
// CTA 64: the batch-invariant hm chain.
// Per k: 1 LDG.128 (4 weights) + 2 LDS.64 h-broadcasts + 4 pk2 + 8 FFMA2.
__global__ void __launch_bounds__(192, 1)
k_scan(const float* __restrict__ bhhx, const float* __restrict__ bhhm) {
    __shared__ ull h2a[2][OUTD];      // h packed: h2a[p][k] = (h[2p][k], h[2p+1][k])
    __shared__ ull gh2s[2][G3];       // gh packed over same b-pairs
    __shared__ float hm_s[OUTD];      // hm branch state
    __shared__ float ghm_s[G3];       // hm branch gates
    const int tid = threadIdx.x;
    const int j0 = 4 * tid;           // this thread's four gate columns
    const int d0 = tid, d1 = tid + 192;  // update dims (d1 valid if tid<64)

    if (blockIdx.x < 64) {
        const int bb = blockIdx.x * 4;
        for (int i = tid; i < 2 * OUTD; i += 192) ((ull*)h2a)[i] = 0ull;
        const float4 bh4 = *(const float4*)&bhhx[j0];
        __syncthreads();
        for (int t = 0; t < TST; t++) {
            // prefetch gi gates for this step (independent of k-loop)
            float gr0[4], gz0[4], gn0[4], gr1[4], gz1[4], gn1[4];
#pragma unroll
            for (int b = 0; b < 4; b++) {
                const float* gi = &d_gi[((size_t)(bb + b) * TST + t) * G3];
                gr0[b] = gi[d0]; gz0[b] = gi[OUTD + d0]; gn0[b] = gi[2 * OUTD + d0];
                if (tid < 64) {
                    gr1[b] = gi[d1]; gz1[b] = gi[OUTD + d1]; gn1[b] = gi[2 * OUTD + d1];
                }
            }
            ull a00 = pk2(bh4.x, bh4.x), a01 = a00;
            ull a10 = pk2(bh4.y, bh4.y), a11 = a10;
            ull a20 = pk2(bh4.z, bh4.z), a21 = a20;
            ull a30 = pk2(bh4.w, bh4.w), a31 = a30;
#pragma unroll 16
            for (int k = 0; k < OUTD; k++) {
                const float4 w4 = *(const float4*)&d_whhT[k * G3 + j0];
                const ull h01 = h2a[0][k], h23 = h2a[1][k];
                ull wd;
                wd = pk2(w4.x, w4.x); fma2(a00, h01, wd); fma2(a01, h23, wd);
                wd = pk2(w4.y, w4.y); fma2(a10, h01, wd); fma2(a11, h23, wd);
                wd = pk2(w4.z, w4.z); fma2(a20, h01, wd); fma2(a21, h23, wd);
                wd = pk2(w4.w, w4.w); fma2(a30, h01, wd); fma2(a31, h23, wd);
            }
            gh2s[0][j0 + 0] = a00; gh2s[0][j0 + 1] = a10;
            gh2s[0][j0 + 2] = a20; gh2s[0][j0 + 3] = a30;
            gh2s[1][j0 + 0] = a01; gh2s[1][j0 + 1] = a11;
            gh2s[1][j0 + 2] = a21; gh2s[1][j0 + 3] = a31;
            __syncthreads();
            // GRU update for dims d0 (all threads) and d1 (tid<64)
#pragma unroll
            for (int p = 0; p < 2; p++) {
                float2 ghr = upk2(gh2s[p][d0]);
                float2 ghz = upk2(gh2s[p][OUTD + d0]);
                float2 ghn = upk2(gh2s[p][2 * OUTD + d0]);
                float2 hold = upk2(h2a[p][d0]);
                const int b0 = 2 * p, b1 = 2 * p + 1;
                float r0 = fsig(gr0[b0] + ghr.x), r1 = fsig(gr0[b1] + ghr.y);
                float z0 = fsig(gz0[b0] + ghz.x), z1 = fsig(gz0[b1] + ghz.y);
                float n0 = ftanh(gn0[b0] + r0 * ghn.x), n1 = ftanh(gn0[b1] + r1 * ghn.y);
                float hn0 = (1.0f - z0) * n0 + z0 * hold.x;
                float hn1 = (1.0f - z1) * n1 + z1 * hold.y;
                h2a[p][d0] = pk2(hn0, hn1);
            }
            if (tid < 64) {
#pragma unroll
                for (int p = 0; p < 2; p++) {
                    float2 ghr = upk2(gh2s[p][d1]);
                    float2 ghz = upk2(gh2s[p][OUTD + d1]);
                    float2 ghn = upk2(gh2s[p][2 * OUTD + d1]);
                    float2 hold = upk2(h2a[p][d1]);
                    const int b0 = 2 * p, b1 = 2 * p + 1;
                    float r0 = fsig(gr1[b0] + ghr.x), r1 = fsig(gr1[b1] + ghr.y);
                    float z0 = fsig(gz1[b0] + ghz.x), z1 = fsig(gz1[b1] + ghz.y);
                    float n0 = ftanh(gn1[b0] + r0 * ghn.x), n1 = ftanh(gn1[b1] + r1 * ghn.y);
                    float hn0 = (1.0f - z0) * n0 + z0 * hold.x;
                    float hn1 = (1.0f - z1) * n1 + z1 * hold.y;
                    h2a[p][d1] = pk2(hn0, hn1);
                }
            }
            __syncthreads();
        }
        // write out final hx
        for (int d = tid; d < OUTD; d += 192) {
#pragma unroll
            for (int p = 0; p < 2; p++) {
                float2 h = upk2(h2a[p][d]);
                d_hxf[(bb + 2 * p) * OUTD + d] = h.x;
                d_hxf[(bb + 2 * p + 1) * OUTD + d] = h.y;
            }
        }
    } else {
        // hm chain: single batch-invariant recurrence
        for (int i = tid; i < OUTD; i += 192) hm_s[i] = 0.0f;
        const float4 bh4 = *(const float4*)&bhhm[j0];
        __syncthreads();
        for (int t = 0; t < TST; t++) {
            float gr0v = 0, gz0v = 0, gn0v = 0, gr1v = 0, gz1v = 0, gn1v = 0;
            {
                const float* gi = &d_gim[t * G3];
                gr0v = gi[d0]; gz0v = gi[OUTD + d0]; gn0v = gi[2 * OUTD + d0];
                if (tid < 64) {
                    gr1v = gi[d1]; gz1v = gi[OUTD + d1]; gn1v = gi[2 * OUTD + d1];
                }
            }
            float a0 = bh4.x, a1 = bh4.y, a2 = bh4.z, a3 = bh4.w;
#pragma unroll 16
            for (int k = 0; k < OUTD; k++) {
                const float4 w4 = *(const float4*)&d_whhmT[k * G3 + j0];
                const float hk = hm_s[k];
                a0 = fmaf(hk, w4.x, a0); a1 = fmaf(hk, w4.y, a1);
                a2 = fmaf(hk, w4.z, a2); a3 = fmaf(hk, w4.w, a3);
            }
            ghm_s[j0 + 0] = a0; ghm_s[j0 + 1] = a1;
            ghm_s[j0 + 2] = a2; ghm_s[j0 + 3] = a3;
            __syncthreads();
            {
                float rr = fsig(gr0v + ghm_s[d0]);
                float zz = fsig(gz0v + ghm_s[OUTD + d0]);
                float nn = ftanh(gn0v + rr * ghm_s[2 * OUTD + d0]);
                hm_s[d0] = (1.0f - zz) * nn + zz * hm_s[d0];
            }
            if (tid < 64) {
                float rr = fsig(gr1v + ghm_s[d1]);
                float zz = fsig(gz1v + ghm_s[OUTD + d1]);
                float nn = ftanh(gn1v + rr * ghm_s[2 * OUTD + d1]);
                hm_s[d1] = (1.0f - zz) * nn + zz * hm_s[d1];
            }
            __syncthreads();
        }
        for (int d = tid; d < OUTD; d += 192) d_hmf[d] = hm_s[d];
    }
}

// ---------------- k_final: cosine gate + blend -----------------------------
__global__ void k_final(const float* __restrict__ Wsx, const float* __restrict__ bsx,
                        const float* __restrict__ Wsm, const float* __restrict__ bsm,
                        float* __restrict__ out) {
    const int b = blockIdx.x, lane = threadIdx.x;  // 256 x 32
    float hx[8], hm[8];
#pragma unroll
    for (int i = 0; i < 8; i++) {
        hx[i] = d_hxf[b * OUTD + lane * 8 + i];
        hm[i] = d_hmf[lane * 8 + i];
    }
    float qx[4], qm[4];
#pragma unroll
    for (int s = 0; s < 4; s++) {
        float ax = 0.0f, am = 0.0f;
#pragma unroll
        for (int i = 0; i < 8; i++) {
            ax = fmaf(hx[i], Wsx[s * OUTD + lane * 8 + i], ax);
            am = fmaf(hm[i], Wsm[s * OUTD + lane * 8 + i], am);
        }
        for (int off = 16; off; off >>= 1) {
            ax += __shfl_xor_sync(0xFFFFFFFFu, ax, off);
            am += __shfl_xor_sync(0xFFFFFFFFu, am, off);
        }
        qx[s] = ax + bsx[s];
        qm[s] = am + bsm[s];
    }
    float num = 0.0f, nx = 0.0f, nm = 0.0f;
#pragma unroll
    for (int s = 0; s < 4; s++) {
        num = fmaf(qx[s], qm[s], num);
        nx = fmaf(qx[s], qx[s], nx);
        nm = fmaf(qm[s], qm[s], nm);
    }
    float den = fmaxf(sqrtf(nx), 1e-8f) * fmaxf(sqrtf(nm), 1e-8f);
    float g = 1.0f / (1.0f + expf(-num / den));
#pragma unroll
    for (int i = 0; i < 8; i++)
        out[b * OUTD + lane * 8 + i] = g * hx[i] + (1.0f - g) * hm[i];
}

// ---------------- launcher -------------------------------------------------
// Launch #4 = k_scan (ncu-profiled slot) to verify the new scan structure.
extern "C" void kernel_launch(void* const* d_in, const int* in_sizes, int n_in,
                              void* d_out, int out_size) {
    const float* x      = (const float*)d_in[0];
    const float* W_emb  = (const float*)d_in[1];
    const float* b_emb  = (const float*)d_in[2];
    const float* gamma  = (const float*)d_in[3];
    const float* beta   = (const float*)d_in[4];
    const float* memory = (const float*)d_in[5];
    const float* w_ih_x = (const float*)d_in[6];
    const float* w_hh_x = (const float*)d_in[7];
    const float* b_ih_x = (const float*)d_in[8];
    const float* b_hh_x = (const float*)d_in[9];
    const float* w_ih_m = (const float*)d_in[10];
    const float* w_hh_m = (const float*)d_in[11];
    const float* b_ih_m = (const float*)d_in[12];
    const float* b_hh_m = (const float*)d_in[13];
    const float* W_sx   = (const float*)d_in[14];
    const float* b_sx   = (const float*)d_in[15];
    const float* W_sm   = (const float*)d_in[16];
    const float* b_sm   = (const float*)d_in[17];
    float* out = (float*)d_out;

    float* ep  = nullptr; cudaGetSymbolAddress((void**)&ep,  d_e);
    float* gip = nullptr; cudaGetSymbolAddress((void**)&gip, d_gi);

    // 1: prep (zero stats + whh transposes + gim)
    k_prep<<<897, 256>>>(w_hh_x, w_hh_m, memory, w_ih_m, b_ih_m);
    // 2: embed GEMM + leaky + BN stats + fused finalize
    k_gemm<INF, 1><<<dim3(256, 8), 256>>>(x, W_emb, b_emb, ep, HID, gamma, beta);
    // 3: big gi GEMM with BN fold on A
    k_gemm<HID, 0><<<dim3(256, 6), 256>>>(ep, w_ih_x, b_ih_x, gip, G3, nullptr, nullptr);
    // 4: recurrences  (ncu-profiled slot)
    k_scan<<<65, 192>>>(b_hh_x, b_hh_m);
    // 5: gate + blend
    k_final<<<256, 32>>>(W_sx, b_sx, W_sm, b_sm, out);
}

// round 8
// speedup vs baseline: 1.4826x; 1.0411x over previous
#include <cuda_runtime.h>
#include <math.h>

#define NBT   32768     // B*T
#define HID   1024
#define G3    768       // 3*OUT
#define OUTD  256
#define TST   128
#define INF   128
#define BATCH 256

typedef unsigned long long ull;

// ---------------- device-global scratch (no allocations allowed) -----------
__device__ __align__(16) float d_e[NBT * HID];     // leaky(embed) activations (raw)
__device__ __align__(16) float d_gi[NBT * G3];     // hoisted input gates (hx GRU)
__device__ __align__(16) float d_gim[TST * G3];    // input gates (hm GRU)
__device__ float d_sum[HID];
__device__ float d_sumsq[HID];
__device__ int   d_ctr;
__device__ __align__(16) float d_scale[HID];
__device__ __align__(16) float d_shift[HID];
// interleaved 2k x 2j scan weights: w2[((k>>1)*G3 + j)*2 + (k&1)] = w[j][k]
__device__ __align__(16) float d_whh2x[OUTD * G3];
__device__ __align__(16) float d_whh2m[OUTD * G3];
__device__ __align__(16) float d_hxf[BATCH * OUTD];
__device__ __align__(16) float d_hmf[OUTD];

// ---------------- packed f32x2 helpers -------------------------------------
__device__ __forceinline__ ull pk2(float lo, float hi) {
    ull r; asm("mov.b64 %0,{%1,%2};" : "=l"(r) : "f"(lo), "f"(hi)); return r;
}
__device__ __forceinline__ void fma2(ull& d, ull a, ull b) {
    asm("fma.rn.f32x2 %0,%1,%2,%3;" : "=l"(d) : "l"(a), "l"(b), "l"(d));
}
__device__ __forceinline__ float2 upk2(ull v) {
    float2 f; asm("mov.b64 {%0,%1},%2;" : "=f"(f.x), "=f"(f.y) : "l"(v)); return f;
}
__device__ __forceinline__ float fsig(float x) {       // sigmoid via MUFU exp
    return 1.0f / (1.0f + __expf(-x));
}
__device__ __forceinline__ float ftanh(float x) {      // tanh via MUFU exp
    return 2.0f / (1.0f + __expf(-2.0f * x)) - 1.0f;
}

// ---------------- k_prep: zero stats + whh re-layouts + gim ----------------
// blocks [0,768): re-layout chunks; [768,896): gim rows; 896: zero stats.
__global__ void k_prep(const float* __restrict__ wx, const float* __restrict__ wm,
                       const float* __restrict__ mem, const float* __restrict__ wim,
                       const float* __restrict__ bim) {
    const int blk = blockIdx.x, tid = threadIdx.x;
    if (blk < 768) {
        const int idx = blk * 256 + tid;          // over G3*OUTD
        const int j = idx / OUTD, k = idx % OUTD;
        const int dst = ((k >> 1) * G3 + j) * 2 + (k & 1);
        d_whh2x[dst] = wx[idx];
        d_whh2m[dst] = wm[idx];
    } else if (blk < 896) {
        const int t = blk - 768;
        const float4* m4 = (const float4*)(mem + t * HID);
        for (int j = tid; j < G3; j += 256) {
            const float4* w4 = (const float4*)(wim + (size_t)j * HID);
            float acc = bim[j];
#pragma unroll 8
            for (int k = 0; k < HID / 4; k++) {
                float4 a = m4[k], b = w4[k];
                acc = fmaf(a.x, b.x, fmaf(a.y, b.y, fmaf(a.z, b.z, fmaf(a.w, b.w, acc))));
            }
            d_gim[t * G3 + j] = acc;
        }
    } else {
        for (int i = tid; i < HID; i += 256) { d_sum[i] = 0.0f; d_sumsq[i] = 0.0f; }
        if (tid == 0) d_ctr = 0;
    }
}

// ---------------- k_gemm: C[M x N] = A'[M x K] @ B[N x K] (+ epilogue) -----
template<int KDIM, int EMBED>
__global__ void __launch_bounds__(256)
k_gemm(const float* __restrict__ A, const float* __restrict__ B,
       const float* __restrict__ bias, float* __restrict__ C, int Nld,
       const float* __restrict__ gamma, const float* __restrict__ beta) {
    __shared__ __align__(16) float As[16][132];
    __shared__ __align__(16) float Bs[16][132];
    const int m0 = blockIdx.x * 128, n0 = blockIdx.y * 128;
    const int tid = threadIdx.x, tx = tid & 15, ty = tid >> 4;

    const int r0 = tid >> 2, qa = tid & 3, r1 = r0 + 64;   // rows within tile

    ull acc[8][4];
#pragma unroll
    for (int i = 0; i < 8; i++) { acc[i][0] = 0; acc[i][1] = 0; acc[i][2] = 0; acc[i][3] = 0; }

    const float* pa0 = &A[(size_t)(m0 + r0) * KDIM + qa * 4];
    const float* pa1 = &A[(size_t)(m0 + r1) * KDIM + qa * 4];
    const float* pb0 = &B[(size_t)(n0 + r0) * KDIM + qa * 4];
    const float* pb1 = &B[(size_t)(n0 + r1) * KDIM + qa * 4];

    float4 ra0 = *(const float4*)pa0;
    float4 ra1 = *(const float4*)pa1;
    float4 rb0 = *(const float4*)pb0;
    float4 rb1 = *(const float4*)pb1;

    const int NC = KDIM / 16;
    for (int kt = 0; kt < NC; kt++) {
        if (!EMBED) {  // BN affine fold on A
            const int kk = kt * 16 + qa * 4;
            float4 sc = *(const float4*)&d_scale[kk];
            float4 sh = *(const float4*)&d_shift[kk];
            ra0.x = fmaf(ra0.x, sc.x, sh.x); ra0.y = fmaf(ra0.y, sc.y, sh.y);
            ra0.z = fmaf(ra0.z, sc.z, sh.z); ra0.w = fmaf(ra0.w, sc.w, sh.w);
            ra1.x = fmaf(ra1.x, sc.x, sh.x); ra1.y = fmaf(ra1.y, sc.y, sh.y);
            ra1.z = fmaf(ra1.z, sc.z, sh.z); ra1.w = fmaf(ra1.w, sc.w, sh.w);
        }
        As[qa * 4 + 0][r0] = ra0.x; As[qa * 4 + 1][r0] = ra0.y;
        As[qa * 4 + 2][r0] = ra0.z; As[qa * 4 + 3][r0] = ra0.w;
        As[qa * 4 + 0][r1] = ra1.x; As[qa * 4 + 1][r1] = ra1.y;
        As[qa * 4 + 2][r1] = ra1.z; As[qa * 4 + 3][r1] = ra1.w;
        Bs[qa * 4 + 0][r0] = rb0.x; Bs[qa * 4 + 1][r0] = rb0.y;
        Bs[qa * 4 + 2][r0] = rb0.z; Bs[qa * 4 + 3][r0] = rb0.w;
        Bs[qa * 4 + 0][r1] = rb1.x; Bs[qa * 4 + 1][r1] = rb1.y;
        Bs[qa * 4 + 2][r1] = rb1.z; Bs[qa * 4 + 3][r1] = rb1.w;
        __syncthreads();
        if (kt + 1 < NC) {
            const int ko = (kt + 1) * 16;
            ra0 = *(const float4*)(pa0 + ko);
            ra1 = *(const float4*)(pa1 + ko);
            rb0 = *(const float4*)(pb0 + ko);
            rb1 = *(const float4*)(pb1 + ko);
        }
#pragma unroll 4
        for (int k = 0; k < 16; k++) {
            float4 af0 = *(const float4*)&As[k][ty * 8];
            float4 af1 = *(const float4*)&As[k][ty * 8 + 4];
            ulonglong2 b01 = *(const ulonglong2*)&Bs[k][tx * 8];
            ulonglong2 b23 = *(const ulonglong2*)&Bs[k][tx * 8 + 4];
            ull ap;
            ap = pk2(af0.x, af0.x);
            fma2(acc[0][0], ap, b01.x); fma2(acc[0][1], ap, b01.y);
            fma2(acc[0][2], ap, b23.x); fma2(acc[0][3], ap, b23.y);
            ap = pk2(af0.y, af0.y);
            fma2(acc[1][0], ap, b01.x); fma2(acc[1][1], ap, b01.y);
            fma2(acc[1][2], ap, b23.x); fma2(acc[1][3], ap, b23.y);
            ap = pk2(af0.z, af0.z);
            fma2(acc[2][0], ap, b01.x); fma2(acc[2][1], ap, b01.y);
            fma2(acc[2][2], ap, b23.x); fma2(acc[2][3], ap, b23.y);
            ap = pk2(af0.w, af0.w);
            fma2(acc[3][0], ap, b01.x); fma2(acc[3][1], ap, b01.y);
            fma2(acc[3][2], ap, b23.x); fma2(acc[3][3], ap, b23.y);
            ap = pk2(af1.x, af1.x);
            fma2(acc[4][0], ap, b01.x); fma2(acc[4][1], ap, b01.y);
            fma2(acc[4][2], ap, b23.x); fma2(acc[4][3], ap, b23.y);
            ap = pk2(af1.y, af1.y);
            fma2(acc[5][0], ap, b01.x); fma2(acc[5][1], ap, b01.y);
            fma2(acc[5][2], ap, b23.x); fma2(acc[5][3], ap, b23.y);
            ap = pk2(af1.z, af1.z);
            fma2(acc[6][0], ap, b01.x); fma2(acc[6][1], ap, b01.y);
            fma2(acc[6][2], ap, b23.x); fma2(acc[6][3], ap, b23.y);
            ap = pk2(af1.w, af1.w);
            fma2(acc[7][0], ap, b01.x); fma2(acc[7][1], ap, b01.y);
            fma2(acc[7][2], ap, b23.x); fma2(acc[7][3], ap, b23.y);
        }
        __syncthreads();
    }

    float bv[8];
#pragma unroll
    for (int c = 0; c < 8; c++) bv[c] = bias[n0 + tx * 8 + c];

    if (EMBED) {
        float ssum[8], ssq[8];
#pragma unroll
        for (int c = 0; c < 8; c++) { ssum[c] = 0.0f; ssq[c] = 0.0f; }
#pragma unroll
        for (int i = 0; i < 8; i++) {
            const int m = m0 + ty * 8 + i;
            float* er = &C[(size_t)m * Nld + n0 + tx * 8];
#pragma unroll
            for (int jj = 0; jj < 4; jj++) {
                float2 v = upk2(acc[i][jj]);
                const int c0 = jj * 2, c1 = jj * 2 + 1;
                float v0 = v.x + bv[c0]; v0 = (v0 >= 0.0f) ? v0 : 0.2f * v0;
                float v1 = v.y + bv[c1]; v1 = (v1 >= 0.0f) ? v1 : 0.2f * v1;
                er[c0] = v0; er[c1] = v1;
                ssum[c0] += v0; ssq[c0] += v0 * v0;
                ssum[c1] += v1; ssq[c1] += v1 * v1;
            }
        }
        float* sb = (float*)As;
        __syncthreads();
#pragma unroll
        for (int c = 0; c < 8; c++) sb[ty * 128 + tx * 8 + c] = ssum[c];
        __syncthreads();
        if (tid < 128) {
            float tot = 0.0f;
#pragma unroll
            for (int rr = 0; rr < 16; rr++) tot += sb[rr * 128 + tid];
            atomicAdd(&d_sum[n0 + tid], tot);
        }
        __syncthreads();
#pragma unroll
        for (int c = 0; c < 8; c++) sb[ty * 128 + tx * 8 + c] = ssq[c];
        __syncthreads();
        if (tid < 128) {
            float tot = 0.0f;
#pragma unroll
            for (int rr = 0; rr < 16; rr++) tot += sb[rr * 128 + tid];
            atomicAdd(&d_sumsq[n0 + tid], tot);
        }
        // fused BN-finalize: last CTA computes scale/shift
        __threadfence();
        __syncthreads();
        __shared__ int last;
        if (tid == 0) {
            int v = atomicAdd(&d_ctr, 1);
            last = (v == (int)(gridDim.x * gridDim.y) - 1);
        }
        __syncthreads();
        if (last) {
            __threadfence();
            for (int h = tid; h < HID; h += 256) {
                float mean = d_sum[h] * (1.0f / 32768.0f);
                float var = d_sumsq[h] * (1.0f / 32768.0f) - mean * mean;
                var = var > 0.0f ? var : 0.0f;
                float sc = gamma[h] * rsqrtf(var + 1e-5f);
                d_scale[h] = sc;
                d_shift[h] = beta[h] - mean * sc;
            }
        }
    } else {
#pragma unroll
        for (int i = 0; i < 8; i++) {
            const int m = m0 + ty * 8 + i;
            float* gr = &C[(size_t)m * Nld + n0 + tx * 8];
#pragma unroll
            for (int jj = 0; jj < 4; jj++) {
                float2 v = upk2(acc[i][jj]);
                gr[jj * 2] = v.x + bv[jj * 2];
                gr[jj * 2 + 1] = v.y + bv[jj * 2 + 1];
            }
        }
    }
}

// ---------------- k_scan: persistent GRU recurrences (384 thr, 2j/thread) --
// CTAs 0..63: hx for 4 batch rows (2 f32x2 b-pairs). CTA 64: hm chain.
// Per 2-k iter: 1 LDG.128 (2j x 2k weights) + 2 LDS.128 + 4 pk2 + 8 FFMA2.
__global__ void __launch_bounds__(384, 1)
k_scan(const float* __restrict__ bhhx, const float* __restrict__ bhhm) {
    __shared__ ull h2a[2][OUTD];      // h2a[p][k] = (h[2p][k], h[2p+1][k])
    __shared__ ull gh2s[2][G3];       // gates packed over b-pairs
    __shared__ float hm_s[OUTD];
    __shared__ float ghm_s[G3];
    const int tid = threadIdx.x;
    const int j0 = 2 * tid;           // this thread's two gate columns

    if (blockIdx.x < 64) {
        const int bb = blockIdx.x * 4;
        for (int i = tid; i < 2 * OUTD; i += 384) ((ull*)h2a)[i] = 0ull;
        const float2 bh2 = *(const float2*)&bhhx[j0];
        const ull bj0 = pk2(bh2.x, bh2.x), bj1 = pk2(bh2.y, bh2.y);
        // packed update mapping: u0 = tid (all), u1 = 384+tid (tid<128)
        const int p0 = tid >> 8, dd0 = tid & 255;
        const int dd1 = 128 + tid;    // pair 1, valid for tid < 128
        __syncthreads();
        for (int t = 0; t < TST; t++) {
            // prefetch gi gates (independent of k-loop; hides DRAM latency)
            float g0r0, g0z0, g0n0, g0r1, g0z1, g0n1;
            {
                const float* giA = &d_gi[((size_t)(bb + 2 * p0) * TST + t) * G3];
                const float* giB = &d_gi[((size_t)(bb + 2 * p0 + 1) * TST + t) * G3];
                g0r0 = giA[dd0]; g0z0 = giA[OUTD + dd0]; g0n0 = giA[2 * OUTD + dd0];
                g0r1 = giB[dd0]; g0z1 = giB[OUTD + dd0]; g0n1 = giB[2 * OUTD + dd0];
            }
            float g1r0 = 0, g1z0 = 0, g1n0 = 0, g1r1 = 0, g1z1 = 0, g1n1 = 0;
            if (tid < 128) {
                const float* giA = &d_gi[((size_t)(bb + 2) * TST + t) * G3];
                const float* giB = &d_gi[((size_t)(bb + 3) * TST + t) * G3];
                g1r0 = giA[dd1]; g1z0 = giA[OUTD + dd1]; g1n0 = giA[2 * OUTD + dd1];
                g1r1 = giB[dd1]; g1z1 = giB[OUTD + dd1]; g1n1 = giB[2 * OUTD + dd1];
            }
            // gh = h @ whh^T + bhh for this thread's two j columns, both pairs
            ull a00 = bj0, a01 = bj0, a10 = bj1, a11 = bj1;  // a[j][pair]
#pragma unroll 8
            for (int k2 = 0; k2 < OUTD / 2; k2++) {
                const float4 w4 = *(const float4*)&d_whh2x[(k2 * G3 + j0) * 2];
                const ulonglong2 hp0 = *(const ulonglong2*)&h2a[0][2 * k2];
                const ulonglong2 hp1 = *(const ulonglong2*)&h2a[1][2 * k2];
                ull wd;
                wd = pk2(w4.x, w4.x); fma2(a00, hp0.x, wd); fma2(a01, hp1.x, wd);
                wd = pk2(w4.y, w4.y); fma2(a00, hp0.y, wd); fma2(a01, hp1.y, wd);
                wd = pk2(w4.z, w4.z); fma2(a10, hp0.x, wd); fma2(a11, hp1.x, wd);
                wd = pk2(w4.w, w4.w); fma2(a10, hp0.y, wd); fma2(a11, hp1.y, wd);
            }
            gh2s[0][j0] = a00; gh2s[0][j0 + 1] = a10;
            gh2s[1][j0] = a01; gh2s[1][j0 + 1] = a11;
            __syncthreads();
            // GRU update: u0 for all threads
            {
                float2 ghr = upk2(gh2s[p0][dd0]);
                float2 ghz = upk2(gh2s[p0][OUTD + dd0]);
                float2 ghn = upk2(gh2s[p0][2 * OUTD + dd0]);
                float2 hold = upk2(h2a[p0][dd0]);
                float r0 = fsig(g0r0 + ghr.x), r1 = fsig(g0r1 + ghr.y);
                float z0 = fsig(g0z0 + ghz.x), z1 = fsig(g0z1 + ghz.y);
                float n0 = ftanh(g0n0 + r0 * ghn.x), n1 = ftanh(g0n1 + r1 * ghn.y);
                h2a[p0][dd0] = pk2((1.0f - z0) * n0 + z0 * hold.x,
                                   (1.0f - z1) * n1 + z1 * hold.y);
            }
            if (tid < 128) {  // u1: pair 1, dims 128..255
                float2 ghr = upk2(gh2s[1][dd1]);
                float2 ghz = upk2(gh2s[1][OUTD + dd1]);
                float2 ghn = upk2(gh2s[1][2 * OUTD + dd1]);
                float2 hold = upk2(h2a[1][dd1]);
                float r0 = fsig(g1r0 + ghr.x), r1 = fsig(g1r1 + ghr.y);
                float z0 = fsig(g1z0 + ghz.x), z1 = fsig(g1z1 + ghz.y);
                float n0 = ftanh(g1n0 + r0 * ghn.x), n1 = ftanh(g1n1 + r1 * ghn.y);
                h2a[1][dd1] = pk2((1.0f - z0) * n0 + z0 * hold.x,
                                  (1.0f - z1) * n1 + z1 * hold.y);
            }
            __syncthreads();
        }
        for (int d = tid; d < OUTD; d += 384) {
#pragma unroll
            for (int p = 0; p < 2; p++) {
                float2 h = upk2(h2a[p][d]);
                d_hxf[(bb + 2 * p) * OUTD + d] = h.x;
                d_hxf[(bb + 2 * p + 1) * OUTD + d] = h.y;
            }
        }
    } else {
        // hm chain: single batch-invariant recurrence
        for (int i = tid; i < OUTD; i += 384) hm_s[i] = 0.0f;
        const float2 bh2 = *(const float2*)&bhhm[j0];
        __syncthreads();
        for (int t = 0; t < TST; t++) {
            float grv = 0, gzv = 0, gnv = 0;
            if (tid < OUTD) {
                const float* gi = &d_gim[t * G3];
                grv = gi[tid]; gzv = gi[OUTD + tid]; gnv = gi[2 * OUTD + tid];
            }
            float a0 = bh2.x, a1 = bh2.y;
#pragma unroll 8
            for (int k2 = 0; k2 < OUTD / 2; k2++) {
                const float4 w4 = *(const float4*)&d_whh2m[(k2 * G3 + j0) * 2];
                const float2 h2 = *(const float2*)&hm_s[2 * k2];
                a0 = fmaf(h2.x, w4.x, fmaf(h2.y, w4.y, a0));
                a1 = fmaf(h2.x, w4.z, fmaf(h2.y, w4.w, a1));
            }
            ghm_s[j0] = a0; ghm_s[j0 + 1] = a1;
            __syncthreads();
            if (tid < OUTD) {
                float rr = fsig(grv + ghm_s[tid]);
                float zz = fsig(gzv + ghm_s[OUTD + tid]);
                float nn = ftanh(gnv + rr * ghm_s[2 * OUTD + tid]);
                hm_s[tid] = (1.0f - zz) * nn + zz * hm_s[tid];
            }
            __syncthreads();
        }
        for (int d = tid; d < OUTD; d += 384) d_hmf[d] = hm_s[d];
    }
}

// ---------------- k_final: cosine gate + blend -----------------------------
__global__ void k_final(const float* __restrict__ Wsx, const float* __restrict__ bsx,
                        const float* __restrict__ Wsm, const float* __restrict__ bsm,
                        float* __restrict__ out) {
    const int b = blockIdx.x, lane = threadIdx.x;  // 256 x 32
    float hx[8], hm[8];
#pragma unroll
    for (int i = 0; i < 8; i++) {
        hx[i] = d_hxf[b * OUTD + lane * 8 + i];
        hm[i] = d_hmf[lane * 8 + i];
    }
    float qx[4], qm[4];
#pragma unroll
    for (int s = 0; s < 4; s++) {
        float ax = 0.0f, am = 0.0f;
#pragma unroll
        for (int i = 0; i < 8; i++) {
            ax = fmaf(hx[i], Wsx[s * OUTD + lane * 8 + i], ax);
            am = fmaf(hm[i], Wsm[s * OUTD + lane * 8 + i], am);
        }
        for (int off = 16; off; off >>= 1) {
            ax += __shfl_xor_sync(0xFFFFFFFFu, ax, off);
            am += __shfl_xor_sync(0xFFFFFFFFu, am, off);
        }
        qx[s] = ax + bsx[s];
        qm[s] = am + bsm[s];
    }
    float num = 0.0f, nx = 0.0f, nm = 0.0f;
#pragma unroll
    for (int s = 0; s < 4; s++) {
        num = fmaf(qx[s], qm[s], num);
        nx = fmaf(qx[s], qx[s], nx);
        nm = fmaf(qm[s], qm[s], nm);
    }
    float den = fmaxf(sqrtf(nx), 1e-8f) * fmaxf(sqrtf(nm), 1e-8f);
    float g = 1.0f / (1.0f + expf(-num / den));
#pragma unroll
    for (int i = 0; i < 8; i++)
        out[b * OUTD + lane * 8 + i] = g * hx[i] + (1.0f - g) * hm[i];
}

// ---------------- launcher -------------------------------------------------
// Launch #4 = k_scan (ncu-profiled slot).
extern "C" void kernel_launch(void* const* d_in, const int* in_sizes, int n_in,
                              void* d_out, int out_size) {
    const float* x      = (const float*)d_in[0];
    const float* W_emb  = (const float*)d_in[1];
    const float* b_emb  = (const float*)d_in[2];
    const float* gamma  = (const float*)d_in[3];
    const float* beta   = (const float*)d_in[4];
    const float* memory = (const float*)d_in[5];
    const float* w_ih_x = (const float*)d_in[6];
    const float* w_hh_x = (const float*)d_in[7];
    const float* b_ih_x = (const float*)d_in[8];
    const float* b_hh_x = (const float*)d_in[9];
    const float* w_ih_m = (const float*)d_in[10];
    const float* w_hh_m = (const float*)d_in[11];
    const float* b_ih_m = (const float*)d_in[12];
    const float* b_hh_m = (const float*)d_in[13];
    const float* W_sx   = (const float*)d_in[14];
    const float* b_sx   = (const float*)d_in[15];
    const float* W_sm   = (const float*)d_in[16];
    const float* b_sm   = (const float*)d_in[17];
    float* out = (float*)d_out;

    float* ep  = nullptr; cudaGetSymbolAddress((void**)&ep,  d_e);
    float* gip = nullptr; cudaGetSymbolAddress((void**)&gip, d_gi);

    // 1: prep (zero stats + whh interleaved re-layout + gim)
    k_prep<<<897, 256>>>(w_hh_x, w_hh_m, memory, w_ih_m, b_ih_m);
    // 2: embed GEMM + leaky + BN stats + fused finalize
    k_gemm<INF, 1><<<dim3(256, 8), 256>>>(x, W_emb, b_emb, ep, HID, gamma, beta);
    // 3: big gi GEMM with BN fold on A
    k_gemm<HID, 0><<<dim3(256, 6), 256>>>(ep, w_ih_x, b_ih_x, gip, G3, nullptr, nullptr);
    // 4: recurrences  (ncu-profiled slot)
    k_scan<<<65, 384>>>(b_hh_x, b_hh_m);
    // 5: gate + blend
    k_final<<<256, 32>>>(W_sx, b_sx, W_sm, b_sm, out);
}

// round 11
// speedup vs baseline: 1.8466x; 1.2455x over previous
#include <cuda_runtime.h>
#include <cuda_bf16.h>
#include <stdint.h>
#include <math.h>

#define NBT   32768     // B*T
#define HID   1024
#define G3    768       // 3*OUT
#define OUTD  256
#define TST   128
#define INF   128
#define BATCH 256

typedef unsigned long long ull;

// ---------------- device-global scratch (no allocations allowed) -----------
__device__ __align__(16) float d_e[NBT * HID];     // leaky(embed) activations (raw)
__device__ __align__(16) float d_gi[NBT * G3];     // hoisted input gates (hx GRU)
__device__ __align__(16) float d_gim[TST * G3];    // input gates (hm GRU)
__device__ float d_sum[HID];
__device__ float d_sumsq[HID];
__device__ int   d_ctr;
__device__ __align__(16) float d_scale[HID];
__device__ __align__(16) float d_shift[HID];
// bf16 split operands for the tensor-core gi GEMM
__device__ __align__(16) __nv_bfloat16 d_ehi[NBT * HID];
__device__ __align__(16) __nv_bfloat16 d_elo[NBT * HID];
__device__ __align__(16) __nv_bfloat16 d_whi[G3 * HID];
__device__ __align__(16) __nv_bfloat16 d_wlo[G3 * HID];
// interleaved 2k x 2j scan weights
__device__ __align__(16) float d_whh2x[OUTD * G3];
__device__ __align__(16) float d_whh2m[OUTD * G3];
__device__ __align__(16) float d_hxf[BATCH * OUTD];
__device__ __align__(16) float d_hmf[OUTD];

// ---------------- packed f32x2 helpers -------------------------------------
__device__ __forceinline__ ull pk2(float lo, float hi) {
    ull r; asm("mov.b64 %0,{%1,%2};" : "=l"(r) : "f"(lo), "f"(hi)); return r;
}
__device__ __forceinline__ void fma2(ull& d, ull a, ull b) {
    asm("fma.rn.f32x2 %0,%1,%2,%3;" : "=l"(d) : "l"(a), "l"(b), "l"(d));
}
__device__ __forceinline__ float2 upk2(ull v) {
    float2 f; asm("mov.b64 {%0,%1},%2;" : "=f"(f.x), "=f"(f.y) : "l"(v)); return f;
}
__device__ __forceinline__ float fsig(float x) { return 1.0f / (1.0f + __expf(-x)); }
__device__ __forceinline__ float ftanh(float x) { return 2.0f / (1.0f + __expf(-2.0f * x)) - 1.0f; }

// ---------------- HMMA m16n8k16 bf16 (baseline PTX, no 'a' features) -------
__device__ __forceinline__ void mma16816(float* d, const unsigned int* a,
                                         const unsigned int* b) {
    asm volatile(
        "mma.sync.aligned.m16n8k16.row.col.f32.bf16.bf16.f32 "
        "{%0,%1,%2,%3}, {%4,%5,%6,%7}, {%8,%9}, {%0,%1,%2,%3};"
        : "+f"(d[0]), "+f"(d[1]), "+f"(d[2]), "+f"(d[3])
        : "r"(a[0]), "r"(a[1]), "r"(a[2]), "r"(a[3]), "r"(b[0]), "r"(b[1]));
}

// ---------------- k_prep: zero stats + whh re-layouts + gim ----------------
__global__ void k_prep(const float* __restrict__ wx, const float* __restrict__ wm,
                       const float* __restrict__ mem, const float* __restrict__ wim,
                       const float* __restrict__ bim) {
    const int blk = blockIdx.x, tid = threadIdx.x;
    if (blk < 768) {
        const int idx = blk * 256 + tid;
        const int j = idx / OUTD, k = idx % OUTD;
        const int dst = ((k >> 1) * G3 + j) * 2 + (k & 1);
        d_whh2x[dst] = wx[idx];
        d_whh2m[dst] = wm[idx];
    } else if (blk < 896) {
        const int t = blk - 768;
        const float4* m4 = (const float4*)(mem + t * HID);
        for (int j = tid; j < G3; j += 256) {
            const float4* w4 = (const float4*)(wim + (size_t)j * HID);
            float acc = bim[j];
#pragma unroll 8
            for (int k = 0; k < HID / 4; k++) {
                float4 a = m4[k], b = w4[k];
                acc = fmaf(a.x, b.x, fmaf(a.y, b.y, fmaf(a.z, b.z, fmaf(a.w, b.w, acc))));
            }
            d_gim[t * G3 + j] = acc;
        }
    } else {
        for (int i = tid; i < HID; i += 256) { d_sum[i] = 0.0f; d_sumsq[i] = 0.0f; }
        if (tid == 0) d_ctr = 0;
    }
}

// ---------------- k_embed: e = leaky(x@W^T+b) + BN stats + finalize --------
__global__ void __launch_bounds__(256)
k_embed(const float* __restrict__ A, const float* __restrict__ B,
        const float* __restrict__ bias,
        const float* __restrict__ gamma, const float* __restrict__ beta) {
    __shared__ __align__(16) float As[16][132];
    __shared__ __align__(16) float Bs[16][132];
    const int m0 = blockIdx.x * 128, n0 = blockIdx.y * 128;
    const int tid = threadIdx.x, tx = tid & 15, ty = tid >> 4;
    const int r0 = tid >> 2, qa = tid & 3, r1 = r0 + 64;

    ull acc[8][4];
#pragma unroll
    for (int i = 0; i < 8; i++) {
#pragma unroll
        for (int j = 0; j < 4; j++) { acc[i][j] = 0ull; }
    }

    const float* pa0 = &A[(size_t)(m0 + r0) * INF + qa * 4];
    const float* pa1 = &A[(size_t)(m0 + r1) * INF + qa * 4];
    const float* pb0 = &B[(size_t)(n0 + r0) * INF + qa * 4];
    const float* pb1 = &B[(size_t)(n0 + r1) * INF + qa * 4];

    float4 ra0 = *(const float4*)pa0;
    float4 ra1 = *(const float4*)pa1;
    float4 rb0 = *(const float4*)pb0;
    float4 rb1 = *(const float4*)pb1;

    const int NC = INF / 16;
    for (int kt = 0; kt < NC; kt++) {
        As[qa * 4 + 0][r0] = ra0.x; As[qa * 4 + 1][r0] = ra0.y;
        As[qa * 4 + 2][r0] = ra0.z; As[qa * 4 + 3][r0] = ra0.w;
        As[qa * 4 + 0][r1] = ra1.x; As[qa * 4 + 1][r1] = ra1.y;
        As[qa * 4 + 2][r1] = ra1.z; As[qa * 4 + 3][r1] = ra1.w;
        Bs[qa * 4 + 0][r0] = rb0.x; Bs[qa * 4 + 1][r0] = rb0.y;
        Bs[qa * 4 + 2][r0] = rb0.z; Bs[qa * 4 + 3][r0] = rb0.w;
        Bs[qa * 4 + 0][r1] = rb1.x; Bs[qa * 4 + 1][r1] = rb1.y;
        Bs[qa * 4 + 2][r1] = rb1.z; Bs[qa * 4 + 3][r1] = rb1.w;
        __syncthreads();
        if (kt + 1 < NC) {
            const int ko = (kt + 1) * 16;
            ra0 = *(const float4*)(pa0 + ko);
            ra1 = *(const float4*)(pa1 + ko);
            rb0 = *(const float4*)(pb0 + ko);
            rb1 = *(const float4*)(pb1 + ko);
        }
#pragma unroll 4
        for (int k = 0; k < 16; k++) {
            float4 af0 = *(const float4*)&As[k][ty * 8];
            float4 af1 = *(const float4*)&As[k][ty * 8 + 4];
            ulonglong2 b01 = *(const ulonglong2*)&Bs[k][tx * 8];
            ulonglong2 b23 = *(const ulonglong2*)&Bs[k][tx * 8 + 4];
            float av[8];
            av[0] = af0.x; av[1] = af0.y; av[2] = af0.z; av[3] = af0.w;
            av[4] = af1.x; av[5] = af1.y; av[6] = af1.z; av[7] = af1.w;
#pragma unroll
            for (int i = 0; i < 8; i++) {
                ull ap = pk2(av[i], av[i]);
                fma2(acc[i][0], ap, b01.x);
                fma2(acc[i][1], ap, b01.y);
                fma2(acc[i][2], ap, b23.x);
                fma2(acc[i][3], ap, b23.y);
            }
        }
        __syncthreads();
    }

    float bv[8];
#pragma unroll
    for (int c = 0; c < 8; c++) { bv[c] = bias[n0 + tx * 8 + c]; }

    float ssum[8], ssq[8];
#pragma unroll
    for (int c = 0; c < 8; c++) { ssum[c] = 0.0f; ssq[c] = 0.0f; }
#pragma unroll
    for (int i = 0; i < 8; i++) {
        const int m = m0 + ty * 8 + i;
        float* er = &d_e[(size_t)m * HID + n0 + tx * 8];
#pragma unroll
        for (int jj = 0; jj < 4; jj++) {
            float2 v = upk2(acc[i][jj]);
            const int c0 = jj * 2, c1 = jj * 2 + 1;
            float v0 = v.x + bv[c0]; v0 = (v0 >= 0.0f) ? v0 : 0.2f * v0;
            float v1 = v.y + bv[c1]; v1 = (v1 >= 0.0f) ? v1 : 0.2f * v1;
            er[c0] = v0; er[c1] = v1;
            ssum[c0] += v0; ssq[c0] += v0 * v0;
            ssum[c1] += v1; ssq[c1] += v1 * v1;
        }
    }
    float* sb = (float*)As;
    __syncthreads();
#pragma unroll
    for (int c = 0; c < 8; c++) { sb[ty * 128 + tx * 8 + c] = ssum[c]; }
    __syncthreads();
    if (tid < 128) {
        float tot = 0.0f;
#pragma unroll
        for (int rr = 0; rr < 16; rr++) { tot += sb[rr * 128 + tid]; }
        atomicAdd(&d_sum[n0 + tid], tot);
    }
    __syncthreads();
#pragma unroll
    for (int c = 0; c < 8; c++) { sb[ty * 128 + tx * 8 + c] = ssq[c]; }
    __syncthreads();
    if (tid < 128) {
        float tot = 0.0f;
#pragma unroll
        for (int rr = 0; rr < 16; rr++) { tot += sb[rr * 128 + tid]; }
        atomicAdd(&d_sumsq[n0 + tid], tot);
    }
    __threadfence();
    __syncthreads();
    __shared__ int last;
    if (tid == 0) {
        int v = atomicAdd(&d_ctr, 1);
        last = (v == (int)(gridDim.x * gridDim.y) - 1) ? 1 : 0;
    }
    __syncthreads();
    if (last) {
        __threadfence();
        for (int h = tid; h < HID; h += 256) {
            float mean = d_sum[h] * (1.0f / 32768.0f);
            float var = d_sumsq[h] * (1.0f / 32768.0f) - mean * mean;
            var = var > 0.0f ? var : 0.0f;
            float sc = gamma[h] * rsqrtf(var + 1e-5f);
            d_scale[h] = sc;
            d_shift[h] = beta[h] - mean * sc;
        }
    }
}

// ---------------- k_convert: bf16 hi/lo split of BN(e) and w_ih_x ----------
__global__ void k_convert(const float* __restrict__ wih) {
    const int tid = threadIdx.x;
    if (blockIdx.x < 16384) {
        const size_t base = (size_t)blockIdx.x * 2048 + (size_t)tid * 8;
        const int k0 = (int)(base & (HID - 1));
        float4 v0 = *(const float4*)&d_e[base];
        float4 v1 = *(const float4*)&d_e[base + 4];
        float4 sc0 = *(const float4*)&d_scale[k0];
        float4 sc1 = *(const float4*)&d_scale[k0 + 4];
        float4 sh0 = *(const float4*)&d_shift[k0];
        float4 sh1 = *(const float4*)&d_shift[k0 + 4];
        float v[8];
        v[0] = fmaf(v0.x, sc0.x, sh0.x); v[1] = fmaf(v0.y, sc0.y, sh0.y);
        v[2] = fmaf(v0.z, sc0.z, sh0.z); v[3] = fmaf(v0.w, sc0.w, sh0.w);
        v[4] = fmaf(v1.x, sc1.x, sh1.x); v[5] = fmaf(v1.y, sc1.y, sh1.y);
        v[6] = fmaf(v1.z, sc1.z, sh1.z); v[7] = fmaf(v1.w, sc1.w, sh1.w);
        __nv_bfloat16 h[8];
        __nv_bfloat16 l[8];
#pragma unroll
        for (int i = 0; i < 8; i++) {
            h[i] = __float2bfloat16(v[i]);
            l[i] = __float2bfloat16(v[i] - __bfloat162float(h[i]));
        }
        *(uint4*)&d_ehi[base] = *(uint4*)h;
        *(uint4*)&d_elo[base] = *(uint4*)l;
    } else {
        const size_t base = (size_t)(blockIdx.x - 16384) * 2048 + (size_t)tid * 8;
        float4 v0 = *(const float4*)&wih[base];
        float4 v1 = *(const float4*)&wih[base + 4];
        float v[8];
        v[0] = v0.x; v[1] = v0.y; v[2] = v0.z; v[3] = v0.w;
        v[4] = v1.x; v[5] = v1.y; v[6] = v1.z; v[7] = v1.w;
        __nv_bfloat16 h[8];
        __nv_bfloat16 l[8];
#pragma unroll
        for (int i = 0; i < 8; i++) {
            h[i] = __float2bfloat16(v[i]);
            l[i] = __float2bfloat16(v[i] - __bfloat162float(h[i]));
        }
        *(uint4*)&d_whi[base] = *(uint4*)h;
        *(uint4*)&d_wlo[base] = *(uint4*)l;
    }
}

// ---------------- k_gemm_mma: gi = split-bf16 HMMA GEMM + bias -------------
// CTA tile 128x64, 8 warps (4x2), warp tile 32x32 (2 m-tiles x 4 n-tiles of
// m16n8k16). smem rows padded to 72 bf16 (144 B) -> all fragment loads are
// conflict-free LDS.32. 48 chunks of K=64: Ahi*Bhi + Ahi*Blo + Alo*Bhi.
__global__ void __launch_bounds__(256, 2)
k_gemm_mma(const float* __restrict__ bias) {
    __shared__ __align__(16) __nv_bfloat16 Asm[128 * 72];
    __shared__ __align__(16) __nv_bfloat16 Bsm[64 * 72];
    const int tid = threadIdx.x;
    const int wid = tid >> 5, lane = tid & 31;
    const int m0 = blockIdx.x * 128, n0 = blockIdx.y * 64;
    const int wm = (wid >> 1) * 32;   // warp m offset
    const int wn = (wid & 1) * 32;    // warp n offset
    const int g = lane >> 2, tig = lane & 3;

    float acc[2][4][4];
#pragma unroll
    for (int mt = 0; mt < 2; mt++) {
#pragma unroll
        for (int nt = 0; nt < 4; nt++) {
#pragma unroll
            for (int r = 0; r < 4; r++) { acc[mt][nt][r] = 0.0f; }
        }
    }

    for (int c = 0; c < 48; c++) {
        const __nv_bfloat16* Ap = (c < 32) ? d_ehi : d_elo;
        const __nv_bfloat16* Bp = (c < 16) ? d_whi : ((c < 32) ? d_wlo : d_whi);
        const int kk = (c & 15) * 64;
        // stage A: 128 rows x 64 bf16
#pragma unroll
        for (int it = 0; it < 4; it++) {
            const int idx = tid + it * 256;
            const int row = idx >> 3;
            const int col = (idx & 7) * 8;
            uint4 v = *(const uint4*)(Ap + (size_t)(m0 + row) * HID + kk + col);
            *(uint4*)&Asm[row * 72 + col] = v;
        }
        // stage B: 64 rows x 64 bf16
#pragma unroll
        for (int it = 0; it < 2; it++) {
            const int idx = tid + it * 256;
            const int row = idx >> 3;
            const int col = (idx & 7) * 8;
            uint4 v = *(const uint4*)(Bp + (size_t)(n0 + row) * HID + kk + col);
            *(uint4*)&Bsm[row * 72 + col] = v;
        }
        __syncthreads();
#pragma unroll
        for (int ks = 0; ks < 4; ks++) {
            const int kw = ks * 16;   // bf16 offset of this k16 step
            unsigned int afr[2][4];
#pragma unroll
            for (int mt = 0; mt < 2; mt++) {
                const int ar = wm + mt * 16 + g;
                afr[mt][0] = *(const unsigned int*)&Asm[ar * 72 + kw + tig * 2];
                afr[mt][1] = *(const unsigned int*)&Asm[(ar + 8) * 72 + kw + tig * 2];
                afr[mt][2] = *(const unsigned int*)&Asm[ar * 72 + kw + 8 + tig * 2];
                afr[mt][3] = *(const unsigned int*)&Asm[(ar + 8) * 72 + kw + 8 + tig * 2];
            }
            unsigned int bfr[4][2];
#pragma unroll
            for (int nt = 0; nt < 4; nt++) {
                const int br = wn + nt * 8 + g;
                bfr[nt][0] = *(const unsigned int*)&Bsm[br * 72 + kw + tig * 2];
                bfr[nt][1] = *(const unsigned int*)&Bsm[br * 72 + kw + 8 + tig * 2];
            }
#pragma unroll
            for (int mt = 0; mt < 2; mt++) {
#pragma unroll
                for (int nt = 0; nt < 4; nt++) {
                    mma16816(acc[mt][nt], afr[mt], bfr[nt]);
                }
            }
        }
        __syncthreads();
    }

    // epilogue: each warp owns [wm, wm+32) x [wn, wn+32)
#pragma unroll
    for (int mt = 0; mt < 2; mt++) {
        const int row = m0 + wm + mt * 16 + g;
#pragma unroll
        for (int nt = 0; nt < 4; nt++) {
            const int col = n0 + wn + nt * 8 + tig * 2;
            const float b0 = bias[col], b1 = bias[col + 1];
            float2 v0, v1;
            v0.x = acc[mt][nt][0] + b0; v0.y = acc[mt][nt][1] + b1;
            v1.x = acc[mt][nt][2] + b0; v1.y = acc[mt][nt][3] + b1;
            *(float2*)&d_gi[(size_t)row * G3 + col] = v0;
            *(float2*)&d_gi[(size_t)(row + 8) * G3 + col] = v1;
        }
    }
}

// ---------------- k_scan: persistent GRU recurrences (384 thr, 2j/thread) --
__global__ void __launch_bounds__(384, 1)
k_scan(const float* __restrict__ bhhx, const float* __restrict__ bhhm) {
    __shared__ ull h2a[2][OUTD];
    __shared__ ull gh2s[2][G3];
    __shared__ float hm_s[OUTD];
    __shared__ float ghm_s[G3];
    const int tid = threadIdx.x;
    const int j0 = 2 * tid;

    if (blockIdx.x < 64) {
        const int bb = blockIdx.x * 4;
        for (int i = tid; i < 2 * OUTD; i += 384) { ((ull*)h2a)[i] = 0ull; }
        const float2 bh2 = *(const float2*)&bhhx[j0];
        const ull bj0 = pk2(bh2.x, bh2.x);
        const ull bj1 = pk2(bh2.y, bh2.y);
        const int p0 = tid >> 8, dd0 = tid & 255;
        const int dd1 = 128 + tid;
        __syncthreads();
        for (int t = 0; t < TST; t++) {
            float g0r0, g0z0, g0n0, g0r1, g0z1, g0n1;
            {
                const float* giA = &d_gi[((size_t)(bb + 2 * p0) * TST + t) * G3];
                const float* giB = &d_gi[((size_t)(bb + 2 * p0 + 1) * TST + t) * G3];
                g0r0 = giA[dd0]; g0z0 = giA[OUTD + dd0]; g0n0 = giA[2 * OUTD + dd0];
                g0r1 = giB[dd0]; g0z1 = giB[OUTD + dd0]; g0n1 = giB[2 * OUTD + dd0];
            }
            float g1r0 = 0, g1z0 = 0, g1n0 = 0, g1r1 = 0, g1z1 = 0, g1n1 = 0;
            if (tid < 128) {
                const float* giA = &d_gi[((size_t)(bb + 2) * TST + t) * G3];
                const float* giB = &d_gi[((size_t)(bb + 3) * TST + t) * G3];
                g1r0 = giA[dd1]; g1z0 = giA[OUTD + dd1]; g1n0 = giA[2 * OUTD + dd1];
                g1r1 = giB[dd1]; g1z1 = giB[OUTD + dd1]; g1n1 = giB[2 * OUTD + dd1];
            }
            ull a00 = bj0, a01 = bj0, a10 = bj1, a11 = bj1;
#pragma unroll 8
            for (int k2 = 0; k2 < OUTD / 2; k2++) {
                const float4 w4 = *(const float4*)&d_whh2x[(k2 * G3 + j0) * 2];
                const ulonglong2 hp0 = *(const ulonglong2*)&h2a[0][2 * k2];
                const ulonglong2 hp1 = *(const ulonglong2*)&h2a[1][2 * k2];
                ull wd;
                wd = pk2(w4.x, w4.x); fma2(a00, hp0.x, wd); fma2(a01, hp1.x, wd);
                wd = pk2(w4.y, w4.y); fma2(a00, hp0.y, wd); fma2(a01, hp1.y, wd);
                wd = pk2(w4.z, w4.z); fma2(a10, hp0.x, wd); fma2(a11, hp1.x, wd);
                wd = pk2(w4.w, w4.w); fma2(a10, hp0.y, wd); fma2(a11, hp1.y, wd);
            }
            gh2s[0][j0] = a00; gh2s[0][j0 + 1] = a10;
            gh2s[1][j0] = a01; gh2s[1][j0 + 1] = a11;
            __syncthreads();
            {
                float2 ghr = upk2(gh2s[p0][dd0]);
                float2 ghz = upk2(gh2s[p0][OUTD + dd0]);
                float2 ghn = upk2(gh2s[p0][2 * OUTD + dd0]);
                float2 hold = upk2(h2a[p0][dd0]);
                float r0 = fsig(g0r0 + ghr.x), r1 = fsig(g0r1 + ghr.y);
                float z0 = fsig(g0z0 + ghz.x), z1 = fsig(g0z1 + ghz.y);
                float n0 = ftanh(g0n0 + r0 * ghn.x), n1 = ftanh(g0n1 + r1 * ghn.y);
                h2a[p0][dd0] = pk2((1.0f - z0) * n0 + z0 * hold.x,
                                   (1.0f - z1) * n1 + z1 * hold.y);
            }
            if (tid < 128) {
                float2 ghr = upk2(gh2s[1][dd1]);
                float2 ghz = upk2(gh2s[1][OUTD + dd1]);
                float2 ghn = upk2(gh2s[1][2 * OUTD + dd1]);
                float2 hold = upk2(h2a[1][dd1]);
                float r0 = fsig(g1r0 + ghr.x), r1 = fsig(g1r1 + ghr.y);
                float z0 = fsig(g1z0 + ghz.x), z1 = fsig(g1z1 + ghz.y);
                float n0 = ftanh(g1n0 + r0 * ghn.x), n1 = ftanh(g1n1 + r1 * ghn.y);
                h2a[1][dd1] = pk2((1.0f - z0) * n0 + z0 * hold.x,
                                  (1.0f - z1) * n1 + z1 * hold.y);
            }
            __syncthreads();
        }
        for (int d = tid; d < OUTD; d += 384) {
#pragma unroll
            for (int p = 0; p < 2; p++) {
                float2 h = upk2(h2a[p][d]);
                d_hxf[(bb + 2 * p) * OUTD + d] = h.x;
                d_hxf[(bb + 2 * p + 1) * OUTD + d] = h.y;
            }
        }
    } else {
        for (int i = tid; i < OUTD; i += 384) { hm_s[i] = 0.0f; }
        const float2 bh2 = *(const float2*)&bhhm[j0];
        __syncthreads();
        for (int t = 0; t < TST; t++) {
            float grv = 0, gzv = 0, gnv = 0;
            if (tid < OUTD) {
                const float* gi = &d_gim[t * G3];
                grv = gi[tid]; gzv = gi[OUTD + tid]; gnv = gi[2 * OUTD + tid];
            }
            float a0 = bh2.x, a1 = bh2.y;
#pragma unroll 8
            for (int k2 = 0; k2 < OUTD / 2; k2++) {
                const float4 w4 = *(const float4*)&d_whh2m[(k2 * G3 + j0) * 2];
                const float2 h2 = *(const float2*)&hm_s[2 * k2];
                a0 = fmaf(h2.x, w4.x, fmaf(h2.y, w4.y, a0));
                a1 = fmaf(h2.x, w4.z, fmaf(h2.y, w4.w, a1));
            }
            ghm_s[j0] = a0; ghm_s[j0 + 1] = a1;
            __syncthreads();
            if (tid < OUTD) {
                float rr = fsig(grv + ghm_s[tid]);
                float zz = fsig(gzv + ghm_s[OUTD + tid]);
                float nn = ftanh(gnv + rr * ghm_s[2 * OUTD + tid]);
                hm_s[tid] = (1.0f - zz) * nn + zz * hm_s[tid];
            }
            __syncthreads();
        }
        for (int d = tid; d < OUTD; d += 384) { d_hmf[d] = hm_s[d]; }
    }
}

// ---------------- k_final: cosine gate + blend -----------------------------
__global__ void k_final(const float* __restrict__ Wsx, const float* __restrict__ bsx,
                        const float* __restrict__ Wsm, const float* __restrict__ bsm,
                        float* __restrict__ out) {
    const int b = blockIdx.x, lane = threadIdx.x;
    float hx[8], hm[8];
#pragma unroll
    for (int i = 0; i < 8; i++) {
        hx[i] = d_hxf[b * OUTD + lane * 8 + i];
        hm[i] = d_hmf[lane * 8 + i];
    }
    float qx[4], qm[4];
#pragma unroll
    for (int s = 0; s < 4; s++) {
        float ax = 0.0f, am = 0.0f;
#pragma unroll
        for (int i = 0; i < 8; i++) {
            ax = fmaf(hx[i], Wsx[s * OUTD + lane * 8 + i], ax);
            am = fmaf(hm[i], Wsm[s * OUTD + lane * 8 + i], am);
        }
        for (int off = 16; off; off >>= 1) {
            ax += __shfl_xor_sync(0xFFFFFFFFu, ax, off);
            am += __shfl_xor_sync(0xFFFFFFFFu, am, off);
        }
        qx[s] = ax + bsx[s];
        qm[s] = am + bsm[s];
    }
    float num = 0.0f, nx = 0.0f, nm = 0.0f;
#pragma unroll
    for (int s = 0; s < 4; s++) {
        num = fmaf(qx[s], qm[s], num);
        nx = fmaf(qx[s], qx[s], nx);
        nm = fmaf(qm[s], qm[s], nm);
    }
    float den = fmaxf(sqrtf(nx), 1e-8f) * fmaxf(sqrtf(nm), 1e-8f);
    float g = 1.0f / (1.0f + expf(-num / den));
#pragma unroll
    for (int i = 0; i < 8; i++) {
        out[b * OUTD + lane * 8 + i] = g * hx[i] + (1.0f - g) * hm[i];
    }
}

// ---------------- launcher -------------------------------------------------
// Launch #4 = k_gemm_mma (ncu-profiled slot).
extern "C" void kernel_launch(void* const* d_in, const int* in_sizes, int n_in,
                              void* d_out, int out_size) {
    const float* x      = (const float*)d_in[0];
    const float* W_emb  = (const float*)d_in[1];
    const float* b_emb  = (const float*)d_in[2];
    const float* gamma  = (const float*)d_in[3];
    const float* beta   = (const float*)d_in[4];
    const float* memory = (const float*)d_in[5];
    const float* w_ih_x = (const float*)d_in[6];
    const float* w_hh_x = (const float*)d_in[7];
    const float* b_ih_x = (const float*)d_in[8];
    const float* b_hh_x = (const float*)d_in[9];
    const float* w_ih_m = (const float*)d_in[10];
    const float* w_hh_m = (const float*)d_in[11];
    const float* b_ih_m = (const float*)d_in[12];
    const float* b_hh_m = (const float*)d_in[13];
    const float* W_sx   = (const float*)d_in[14];
    const float* b_sx   = (const float*)d_in[15];
    const float* W_sm   = (const float*)d_in[16];
    const float* b_sm   = (const float*)d_in[17];
    float* out = (float*)d_out;

    // 1: prep (zero stats + whh interleaved re-layout + gim)
    k_prep<<<897, 256>>>(w_hh_x, w_hh_m, memory, w_ih_m, b_ih_m);
    // 2: embed GEMM + leaky + BN stats + fused finalize
    k_embed<<<dim3(256, 8), 256>>>(x, W_emb, b_emb, gamma, beta);
    // 3: bf16 hi/lo split of BN(e) and w_ih_x
    k_convert<<<16768, 256>>>(w_ih_x);
    // 4: HMMA gi GEMM  (ncu-profiled slot)
    k_gemm_mma<<<dim3(256, 12), 256>>>(b_ih_x);
    // 5: recurrences
    k_scan<<<65, 384>>>(b_hh_x, b_hh_m);
    // 6: gate + blend
    k_final<<<256, 32>>>(W_sx, b_sx, W_sm, b_sm, out);
}

// round 12
// speedup vs baseline: 2.1083x; 1.1418x over previous
#include <cuda_runtime.h>
#include <cuda_bf16.h>
#include <stdint.h>
#include <math.h>

#define NBT   32768     // B*T
#define HID   1024
#define G3    768       // 3*OUT
#define OUTD  256
#define TST   128
#define INF   128
#define BATCH 256

typedef unsigned long long ull;

// ---------------- device-global scratch (no allocations allowed) -----------
__device__ __align__(16) float d_e[NBT * HID];     // leaky(embed) activations (raw)
__device__ __align__(16) float d_gi[NBT * G3];     // hoisted input gates (hx GRU)
__device__ __align__(16) float d_gim[TST * G3];    // input gates (hm GRU)
__device__ float d_sum[HID];
__device__ float d_sumsq[HID];
__device__ int   d_ctr;
__device__ __align__(16) float d_scale[HID];
__device__ __align__(16) float d_shift[HID];
// bf16 split operands for the tensor-core gi GEMM
__device__ __align__(16) __nv_bfloat16 d_ehi[NBT * HID];
__device__ __align__(16) __nv_bfloat16 d_elo[NBT * HID];
__device__ __align__(16) __nv_bfloat16 d_whi[G3 * HID];
__device__ __align__(16) __nv_bfloat16 d_wlo[G3 * HID];
// interleaved 2k x 2j scan weights
__device__ __align__(16) float d_whh2x[OUTD * G3];
__device__ __align__(16) float d_whh2m[OUTD * G3];
__device__ __align__(16) float d_hxf[BATCH * OUTD];
__device__ __align__(16) float d_hmf[OUTD];

// ---------------- packed f32x2 helpers -------------------------------------
__device__ __forceinline__ ull pk2(float lo, float hi) {
    ull r; asm("mov.b64 %0,{%1,%2};" : "=l"(r) : "f"(lo), "f"(hi)); return r;
}
__device__ __forceinline__ void fma2(ull& d, ull a, ull b) {
    asm("fma.rn.f32x2 %0,%1,%2,%3;" : "=l"(d) : "l"(a), "l"(b), "l"(d));
}
__device__ __forceinline__ float2 upk2(ull v) {
    float2 f; asm("mov.b64 {%0,%1},%2;" : "=f"(f.x), "=f"(f.y) : "l"(v)); return f;
}
__device__ __forceinline__ float fsig(float x) { return 1.0f / (1.0f + __expf(-x)); }
__device__ __forceinline__ float ftanh(float x) { return 2.0f / (1.0f + __expf(-2.0f * x)) - 1.0f; }

// ---------------- HMMA m16n8k16 bf16 + ldmatrix + cp.async (baseline PTX) --
__device__ __forceinline__ void mma16816(float* d, const unsigned int* a,
                                         const unsigned int* b) {
    asm volatile(
        "mma.sync.aligned.m16n8k16.row.col.f32.bf16.bf16.f32 "
        "{%0,%1,%2,%3}, {%4,%5,%6,%7}, {%8,%9}, {%0,%1,%2,%3};"
        : "+f"(d[0]), "+f"(d[1]), "+f"(d[2]), "+f"(d[3])
        : "r"(a[0]), "r"(a[1]), "r"(a[2]), "r"(a[3]), "r"(b[0]), "r"(b[1]));
}
__device__ __forceinline__ void ldsm4(unsigned int* r, unsigned int saddr) {
    asm volatile(
        "ldmatrix.sync.aligned.m8n8.x4.shared.b16 {%0,%1,%2,%3}, [%4];"
        : "=r"(r[0]), "=r"(r[1]), "=r"(r[2]), "=r"(r[3]) : "r"(saddr));
}
__device__ __forceinline__ void cpasync16(unsigned int saddr, const void* gaddr) {
    asm volatile("cp.async.cg.shared.global [%0], [%1], 16;"
                 :: "r"(saddr), "l"(gaddr));
}
#define CP_COMMIT() asm volatile("cp.async.commit_group;" ::: "memory")
#define CP_WAIT(n)  asm volatile("cp.async.wait_group %0;" :: "n"(n) : "memory")

__device__ __forceinline__ unsigned int smem_to_u32(const void* smem_ptr) {
    unsigned int addr;
    asm("{ .reg .u64 tmp; cvta.to.shared.u64 tmp, %1; cvt.u32.u64 %0, tmp; }"
        : "=r"(addr) : "l"(smem_ptr));
    return addr;
}

// ---------------- k_prep: zero stats + whh re-layouts + gim ----------------
__global__ void k_prep(const float* __restrict__ wx, const float* __restrict__ wm,
                       const float* __restrict__ mem, const float* __restrict__ wim,
                       const float* __restrict__ bim) {
    const int blk = blockIdx.x, tid = threadIdx.x;
    if (blk < 768) {
        const int idx = blk * 256 + tid;
        const int j = idx / OUTD, k = idx % OUTD;
        const int dst = ((k >> 1) * G3 + j) * 2 + (k & 1);
        d_whh2x[dst] = wx[idx];
        d_whh2m[dst] = wm[idx];
    } else if (blk < 896) {
        const int t = blk - 768;
        const float4* m4 = (const float4*)(mem + t * HID);
        for (int j = tid; j < G3; j += 256) {
            const float4* w4 = (const float4*)(wim + (size_t)j * HID);
            float acc = bim[j];
#pragma unroll 8
            for (int k = 0; k < HID / 4; k++) {
                float4 a = m4[k], b = w4[k];
                acc = fmaf(a.x, b.x, fmaf(a.y, b.y, fmaf(a.z, b.z, fmaf(a.w, b.w, acc))));
            }
            d_gim[t * G3 + j] = acc;
        }
    } else {
        for (int i = tid; i < HID; i += 256) { d_sum[i] = 0.0f; d_sumsq[i] = 0.0f; }
        if (tid == 0) d_ctr = 0;
    }
}

// ---------------- k_embed: e = leaky(x@W^T+b) + BN stats + finalize --------
__global__ void __launch_bounds__(256)
k_embed(const float* __restrict__ A, const float* __restrict__ B,
        const float* __restrict__ bias,
        const float* __restrict__ gamma, const float* __restrict__ beta) {
    __shared__ __align__(16) float As[16][132];
    __shared__ __align__(16) float Bs[16][132];
    const int m0 = blockIdx.x * 128, n0 = blockIdx.y * 128;
    const int tid = threadIdx.x, tx = tid & 15, ty = tid >> 4;
    const int r0 = tid >> 2, qa = tid & 3, r1 = r0 + 64;

    ull acc[8][4];
#pragma unroll
    for (int i = 0; i < 8; i++) {
#pragma unroll
        for (int j = 0; j < 4; j++) { acc[i][j] = 0ull; }
    }

    const float* pa0 = &A[(size_t)(m0 + r0) * INF + qa * 4];
    const float* pa1 = &A[(size_t)(m0 + r1) * INF + qa * 4];
    const float* pb0 = &B[(size_t)(n0 + r0) * INF + qa * 4];
    const float* pb1 = &B[(size_t)(n0 + r1) * INF + qa * 4];

    float4 ra0 = *(const float4*)pa0;
    float4 ra1 = *(const float4*)pa1;
    float4 rb0 = *(const float4*)pb0;
    float4 rb1 = *(const float4*)pb1;

    const int NC = INF / 16;
    for (int kt = 0; kt < NC; kt++) {
        As[qa * 4 + 0][r0] = ra0.x; As[qa * 4 + 1][r0] = ra0.y;
        As[qa * 4 + 2][r0] = ra0.z; As[qa * 4 + 3][r0] = ra0.w;
        As[qa * 4 + 0][r1] = ra1.x; As[qa * 4 + 1][r1] = ra1.y;
        As[qa * 4 + 2][r1] = ra1.z; As[qa * 4 + 3][r1] = ra1.w;
        Bs[qa * 4 + 0][r0] = rb0.x; Bs[qa * 4 + 1][r0] = rb0.y;
        Bs[qa * 4 + 2][r0] = rb0.z; Bs[qa * 4 + 3][r0] = rb0.w;
        Bs[qa * 4 + 0][r1] = rb1.x; Bs[qa * 4 + 1][r1] = rb1.y;
        Bs[qa * 4 + 2][r1] = rb1.z; Bs[qa * 4 + 3][r1] = rb1.w;
        __syncthreads();
        if (kt + 1 < NC) {
            const int ko = (kt + 1) * 16;
            ra0 = *(const float4*)(pa0 + ko);
            ra1 = *(const float4*)(pa1 + ko);
            rb0 = *(const float4*)(pb0 + ko);
            rb1 = *(const float4*)(pb1 + ko);
        }
#pragma unroll 4
        for (int k = 0; k < 16; k++) {
            float4 af0 = *(const float4*)&As[k][ty * 8];
            float4 af1 = *(const float4*)&As[k][ty * 8 + 4];
            ulonglong2 b01 = *(const ulonglong2*)&Bs[k][tx * 8];
            ulonglong2 b23 = *(const ulonglong2*)&Bs[k][tx * 8 + 4];
            float av[8];
            av[0] = af0.x; av[1] = af0.y; av[2] = af0.z; av[3] = af0.w;
            av[4] = af1.x; av[5] = af1.y; av[6] = af1.z; av[7] = af1.w;
#pragma unroll
            for (int i = 0; i < 8; i++) {
                ull ap = pk2(av[i], av[i]);
                fma2(acc[i][0], ap, b01.x);
                fma2(acc[i][1], ap, b01.y);
                fma2(acc[i][2], ap, b23.x);
                fma2(acc[i][3], ap, b23.y);
            }
        }
        __syncthreads();
    }

    float bv[8];
#pragma unroll
    for (int c = 0; c < 8; c++) { bv[c] = bias[n0 + tx * 8 + c]; }

    float ssum[8], ssq[8];
#pragma unroll
    for (int c = 0; c < 8; c++) { ssum[c] = 0.0f; ssq[c] = 0.0f; }
#pragma unroll
    for (int i = 0; i < 8; i++) {
        const int m = m0 + ty * 8 + i;
        float* er = &d_e[(size_t)m * HID + n0 + tx * 8];
#pragma unroll
        for (int jj = 0; jj < 4; jj++) {
            float2 v = upk2(acc[i][jj]);
            const int c0 = jj * 2, c1 = jj * 2 + 1;
            float v0 = v.x + bv[c0]; v0 = (v0 >= 0.0f) ? v0 : 0.2f * v0;
            float v1 = v.y + bv[c1]; v1 = (v1 >= 0.0f) ? v1 : 0.2f * v1;
            er[c0] = v0; er[c1] = v1;
            ssum[c0] += v0; ssq[c0] += v0 * v0;
            ssum[c1] += v1; ssq[c1] += v1 * v1;
        }
    }
    float* sb = (float*)As;
    __syncthreads();
#pragma unroll
    for (int c = 0; c < 8; c++) { sb[ty * 128 + tx * 8 + c] = ssum[c]; }
    __syncthreads();
    if (tid < 128) {
        float tot = 0.0f;
#pragma unroll
        for (int rr = 0; rr < 16; rr++) { tot += sb[rr * 128 + tid]; }
        atomicAdd(&d_sum[n0 + tid], tot);
    }
    __syncthreads();
#pragma unroll
    for (int c = 0; c < 8; c++) { sb[ty * 128 + tx * 8 + c] = ssq[c]; }
    __syncthreads();
    if (tid < 128) {
        float tot = 0.0f;
#pragma unroll
        for (int rr = 0; rr < 16; rr++) { tot += sb[rr * 128 + tid]; }
        atomicAdd(&d_sumsq[n0 + tid], tot);
    }
    __threadfence();
    __syncthreads();
    __shared__ int last;
    if (tid == 0) {
        int v = atomicAdd(&d_ctr, 1);
        last = (v == (int)(gridDim.x * gridDim.y) - 1) ? 1 : 0;
    }
    __syncthreads();
    if (last) {
        __threadfence();
        for (int h = tid; h < HID; h += 256) {
            float mean = d_sum[h] * (1.0f / 32768.0f);
            float var = d_sumsq[h] * (1.0f / 32768.0f) - mean * mean;
            var = var > 0.0f ? var : 0.0f;
            float sc = gamma[h] * rsqrtf(var + 1e-5f);
            d_scale[h] = sc;
            d_shift[h] = beta[h] - mean * sc;
        }
    }
}

// ---------------- k_convert: bf16 hi/lo split of BN(e) and w_ih_x ----------
__global__ void k_convert(const float* __restrict__ wih) {
    const int tid = threadIdx.x;
    if (blockIdx.x < 16384) {
        const size_t base = (size_t)blockIdx.x * 2048 + (size_t)tid * 8;
        const int k0 = (int)(base & (HID - 1));
        float4 v0 = *(const float4*)&d_e[base];
        float4 v1 = *(const float4*)&d_e[base + 4];
        float4 sc0 = *(const float4*)&d_scale[k0];
        float4 sc1 = *(const float4*)&d_scale[k0 + 4];
        float4 sh0 = *(const float4*)&d_shift[k0];
        float4 sh1 = *(const float4*)&d_shift[k0 + 4];
        float v[8];
        v[0] = fmaf(v0.x, sc0.x, sh0.x); v[1] = fmaf(v0.y, sc0.y, sh0.y);
        v[2] = fmaf(v0.z, sc0.z, sh0.z); v[3] = fmaf(v0.w, sc0.w, sh0.w);
        v[4] = fmaf(v1.x, sc1.x, sh1.x); v[5] = fmaf(v1.y, sc1.y, sh1.y);
        v[6] = fmaf(v1.z, sc1.z, sh1.z); v[7] = fmaf(v1.w, sc1.w, sh1.w);
        __nv_bfloat16 h[8];
        __nv_bfloat16 l[8];
#pragma unroll
        for (int i = 0; i < 8; i++) {
            h[i] = __float2bfloat16(v[i]);
            l[i] = __float2bfloat16(v[i] - __bfloat162float(h[i]));
        }
        *(uint4*)&d_ehi[base] = *(uint4*)h;
        *(uint4*)&d_elo[base] = *(uint4*)l;
    } else {
        const size_t base = (size_t)(blockIdx.x - 16384) * 2048 + (size_t)tid * 8;
        float4 v0 = *(const float4*)&wih[base];
        float4 v1 = *(const float4*)&wih[base + 4];
        float v[8];
        v[0] = v0.x; v[1] = v0.y; v[2] = v0.z; v[3] = v0.w;
        v[4] = v1.x; v[5] = v1.y; v[6] = v1.z; v[7] = v1.w;
        __nv_bfloat16 h[8];
        __nv_bfloat16 l[8];
#pragma unroll
        for (int i = 0; i < 8; i++) {
            h[i] = __float2bfloat16(v[i]);
            l[i] = __float2bfloat16(v[i] - __bfloat162float(h[i]));
        }
        *(uint4*)&d_whi[base] = *(uint4*)h;
        *(uint4*)&d_wlo[base] = *(uint4*)l;
    }
}

// ---------------- k_gemm_mma: gi = split-bf16 HMMA GEMM + bias -------------
// CTA tile 128x128, 4 warps (2x2), warp tile 64x64 (4 mt x 8 nt).
// ldmatrix.x4 fragment loads; cp.async double-buffered staging.
// 48 chunks of K=64: Ahi*Bhi(16) + Ahi*Blo(16) + Alo*Bhi(16).
#define PITCH 72   // bf16 elements per smem row (144 B, 16B-aligned, LDSM-conflict-free)
#define BUFE  (128 * PITCH)

__global__ void __launch_bounds__(128, 2)
k_gemm_mma(const float* __restrict__ bias) {
    extern __shared__ __nv_bfloat16 sm[];   // [2 bufs][A 128*72 + B 128*72]
    const int tid = threadIdx.x;
    const int wid = tid >> 5, lane = tid & 31;
    const int m0 = blockIdx.x * 128, n0 = blockIdx.y * 128;
    const int wm = (wid >> 1) * 64, wn = (wid & 1) * 64;
    const int g = lane >> 2, tig = lane & 3;
    const unsigned int sbase = smem_to_u32(sm);

    // ldmatrix per-lane address components
    const int a_row_off = (lane & 7) + ((lane >> 3) & 1) * 8;  // within 16-row tile
    const int a_col_off = (lane >> 4) * 8;                     // k offset 0/8
    const int b_row_off = (lane & 7) + (lane >> 4) * 8;        // within 16-n pair
    const int b_col_off = ((lane >> 3) & 1) * 8;               // k offset 0/8

    float acc[4][8][4];
#pragma unroll
    for (int mt = 0; mt < 4; mt++)
#pragma unroll
        for (int nt = 0; nt < 8; nt++)
#pragma unroll
            for (int r = 0; r < 4; r++) { acc[mt][nt][r] = 0.0f; }

    // stage chunk c into buffer buf
    auto stage = [&](int c, int buf) {
        const __nv_bfloat16* Ap = (c < 32) ? d_ehi : d_elo;
        const __nv_bfloat16* Bp = (c < 16) ? d_whi : ((c < 32) ? d_wlo : d_whi);
        const int kk = (c & 15) * 64;
        const unsigned int ab = sbase + (unsigned int)(buf * 2 * BUFE) * 2u;
        const unsigned int bb = ab + (unsigned int)BUFE * 2u;
#pragma unroll
        for (int it = 0; it < 8; it++) {
            const int idx = tid + it * 128;
            const int row = idx >> 3;
            const int col = (idx & 7) * 8;
            cpasync16(ab + (unsigned int)(row * PITCH + col) * 2u,
                      Ap + (size_t)(m0 + row) * HID + kk + col);
            cpasync16(bb + (unsigned int)(row * PITCH + col) * 2u,
                      Bp + (size_t)(n0 + row) * HID + kk + col);
        }
        CP_COMMIT();
    };

    stage(0, 0);
    for (int c = 0; c < 48; c++) {
        const int buf = c & 1;
        if (c + 1 < 48) {
            stage(c + 1, 1 - buf);
            CP_WAIT(1);
        } else {
            CP_WAIT(0);
        }
        __syncthreads();
        const unsigned int ab = sbase + (unsigned int)(buf * 2 * BUFE) * 2u;
        const unsigned int bb = ab + (unsigned int)BUFE * 2u;
#pragma unroll
        for (int ks = 0; ks < 4; ks++) {
            const int kw = ks * 16;
            unsigned int afr[4][4];
#pragma unroll
            for (int mt = 0; mt < 4; mt++) {
                ldsm4(afr[mt], ab + (unsigned int)((wm + mt * 16 + a_row_off) * PITCH
                                                   + kw + a_col_off) * 2u);
            }
            unsigned int bfr[8][2];
#pragma unroll
            for (int p = 0; p < 4; p++) {
                unsigned int tmp[4];
                ldsm4(tmp, bb + (unsigned int)((wn + p * 16 + b_row_off) * PITCH
                                               + kw + b_col_off) * 2u);
                bfr[2 * p][0] = tmp[0]; bfr[2 * p][1] = tmp[1];
                bfr[2 * p + 1][0] = tmp[2]; bfr[2 * p + 1][1] = tmp[3];
            }
#pragma unroll
            for (int mt = 0; mt < 4; mt++)
#pragma unroll
                for (int nt = 0; nt < 8; nt++) { mma16816(acc[mt][nt], afr[mt], bfr[nt]); }
        }
        __syncthreads();
    }

    // epilogue: warp owns [wm, wm+64) x [wn, wn+64)
#pragma unroll
    for (int mt = 0; mt < 4; mt++) {
        const int row = m0 + wm + mt * 16 + g;
#pragma unroll
        for (int nt = 0; nt < 8; nt++) {
            const int col = n0 + wn + nt * 8 + tig * 2;
            const float b0 = bias[col], b1 = bias[col + 1];
            float2 v0, v1;
            v0.x = acc[mt][nt][0] + b0; v0.y = acc[mt][nt][1] + b1;
            v1.x = acc[mt][nt][2] + b0; v1.y = acc[mt][nt][3] + b1;
            *(float2*)&d_gi[(size_t)row * G3 + col] = v0;
            *(float2*)&d_gi[(size_t)(row + 8) * G3 + col] = v1;
        }
    }
}

// ---------------- k_scan: persistent GRU recurrences (384 thr, 2j/thread) --
__global__ void __launch_bounds__(384, 1)
k_scan(const float* __restrict__ bhhx, const float* __restrict__ bhhm) {
    __shared__ ull h2a[2][OUTD];
    __shared__ ull gh2s[2][G3];
    __shared__ float hm_s[OUTD];
    __shared__ float ghm_s[G3];
    const int tid = threadIdx.x;
    const int j0 = 2 * tid;

    if (blockIdx.x < 64) {
        const int bb = blockIdx.x * 4;
        for (int i = tid; i < 2 * OUTD; i += 384) { ((ull*)h2a)[i] = 0ull; }
        const float2 bh2 = *(const float2*)&bhhx[j0];
        const ull bj0 = pk2(bh2.x, bh2.x);
        const ull bj1 = pk2(bh2.y, bh2.y);
        const int p0 = tid >> 8, dd0 = tid & 255;
        const int dd1 = 128 + tid;
        __syncthreads();
        for (int t = 0; t < TST; t++) {
            float g0r0, g0z0, g0n0, g0r1, g0z1, g0n1;
            {
                const float* giA = &d_gi[((size_t)(bb + 2 * p0) * TST + t) * G3];
                const float* giB = &d_gi[((size_t)(bb + 2 * p0 + 1) * TST + t) * G3];
                g0r0 = giA[dd0]; g0z0 = giA[OUTD + dd0]; g0n0 = giA[2 * OUTD + dd0];
                g0r1 = giB[dd0]; g0z1 = giB[OUTD + dd0]; g0n1 = giB[2 * OUTD + dd0];
            }
            float g1r0 = 0, g1z0 = 0, g1n0 = 0, g1r1 = 0, g1z1 = 0, g1n1 = 0;
            if (tid < 128) {
                const float* giA = &d_gi[((size_t)(bb + 2) * TST + t) * G3];
                const float* giB = &d_gi[((size_t)(bb + 3) * TST + t) * G3];
                g1r0 = giA[dd1]; g1z0 = giA[OUTD + dd1]; g1n0 = giA[2 * OUTD + dd1];
                g1r1 = giB[dd1]; g1z1 = giB[OUTD + dd1]; g1n1 = giB[2 * OUTD + dd1];
            }
            ull a00 = bj0, a01 = bj0, a10 = bj1, a11 = bj1;
#pragma unroll 8
            for (int k2 = 0; k2 < OUTD / 2; k2++) {
                const float4 w4 = *(const float4*)&d_whh2x[(k2 * G3 + j0) * 2];
                const ulonglong2 hp0 = *(const ulonglong2*)&h2a[0][2 * k2];
                const ulonglong2 hp1 = *(const ulonglong2*)&h2a[1][2 * k2];
                ull wd;
                wd = pk2(w4.x, w4.x); fma2(a00, hp0.x, wd); fma2(a01, hp1.x, wd);
                wd = pk2(w4.y, w4.y); fma2(a00, hp0.y, wd); fma2(a01, hp1.y, wd);
                wd = pk2(w4.z, w4.z); fma2(a10, hp0.x, wd); fma2(a11, hp1.x, wd);
                wd = pk2(w4.w, w4.w); fma2(a10, hp0.y, wd); fma2(a11, hp1.y, wd);
            }
            gh2s[0][j0] = a00; gh2s[0][j0 + 1] = a10;
            gh2s[1][j0] = a01; gh2s[1][j0 + 1] = a11;
            __syncthreads();
            {
                float2 ghr = upk2(gh2s[p0][dd0]);
                float2 ghz = upk2(gh2s[p0][OUTD + dd0]);
                float2 ghn = upk2(gh2s[p0][2 * OUTD + dd0]);
                float2 hold = upk2(h2a[p0][dd0]);
                float r0 = fsig(g0r0 + ghr.x), r1 = fsig(g0r1 + ghr.y);
                float z0 = fsig(g0z0 + ghz.x), z1 = fsig(g0z1 + ghz.y);
                float n0 = ftanh(g0n0 + r0 * ghn.x), n1 = ftanh(g0n1 + r1 * ghn.y);
                h2a[p0][dd0] = pk2((1.0f - z0) * n0 + z0 * hold.x,
                                   (1.0f - z1) * n1 + z1 * hold.y);
            }
            if (tid < 128) {
                float2 ghr = upk2(gh2s[1][dd1]);
                float2 ghz = upk2(gh2s[1][OUTD + dd1]);
                float2 ghn = upk2(gh2s[1][2 * OUTD + dd1]);
                float2 hold = upk2(h2a[1][dd1]);
                float r0 = fsig(g1r0 + ghr.x), r1 = fsig(g1r1 + ghr.y);
                float z0 = fsig(g1z0 + ghz.x), z1 = fsig(g1z1 + ghz.y);
                float n0 = ftanh(g1n0 + r0 * ghn.x), n1 = ftanh(g1n1 + r1 * ghn.y);
                h2a[1][dd1] = pk2((1.0f - z0) * n0 + z0 * hold.x,
                                  (1.0f - z1) * n1 + z1 * hold.y);
            }
            __syncthreads();
        }
        for (int d = tid; d < OUTD; d += 384) {
#pragma unroll
            for (int p = 0; p < 2; p++) {
                float2 h = upk2(h2a[p][d]);
                d_hxf[(bb + 2 * p) * OUTD + d] = h.x;
                d_hxf[(bb + 2 * p + 1) * OUTD + d] = h.y;
            }
        }
    } else {
        for (int i = tid; i < OUTD; i += 384) { hm_s[i] = 0.0f; }
        const float2 bh2 = *(const float2*)&bhhm[j0];
        __syncthreads();
        for (int t = 0; t < TST; t++) {
            float grv = 0, gzv = 0, gnv = 0;
            if (tid < OUTD) {
                const float* gi = &d_gim[t * G3];
                grv = gi[tid]; gzv = gi[OUTD + tid]; gnv = gi[2 * OUTD + tid];
            }
            float a0 = bh2.x, a1 = bh2.y;
#pragma unroll 8
            for (int k2 = 0; k2 < OUTD / 2; k2++) {
                const float4 w4 = *(const float4*)&d_whh2m[(k2 * G3 + j0) * 2];
                const float2 h2 = *(const float2*)&hm_s[2 * k2];
                a0 = fmaf(h2.x, w4.x, fmaf(h2.y, w4.y, a0));
                a1 = fmaf(h2.x, w4.z, fmaf(h2.y, w4.w, a1));
            }
            ghm_s[j0] = a0; ghm_s[j0 + 1] = a1;
            __syncthreads();
            if (tid < OUTD) {
                float rr = fsig(grv + ghm_s[tid]);
                float zz = fsig(gzv + ghm_s[OUTD + tid]);
                float nn = ftanh(gnv + rr * ghm_s[2 * OUTD + tid]);
                hm_s[tid] = (1.0f - zz) * nn + zz * hm_s[tid];
            }
            __syncthreads();
        }
        for (int d = tid; d < OUTD; d += 384) { d_hmf[d] = hm_s[d]; }
    }
}

// ---------------- k_final: cosine gate + blend -----------------------------
__global__ void k_final(const float* __restrict__ Wsx, const float* __restrict__ bsx,
                        const float* __restrict__ Wsm, const float* __restrict__ bsm,
                        float* __restrict__ out) {
    const int b = blockIdx.x, lane = threadIdx.x;
    float hx[8], hm[8];
#pragma unroll
    for (int i = 0; i < 8; i++) {
        hx[i] = d_hxf[b * OUTD + lane * 8 + i];
        hm[i] = d_hmf[lane * 8 + i];
    }
    float qx[4], qm[4];
#pragma unroll
    for (int s = 0; s < 4; s++) {
        float ax = 0.0f, am = 0.0f;
#pragma unroll
        for (int i = 0; i < 8; i++) {
            ax = fmaf(hx[i], Wsx[s * OUTD + lane * 8 + i], ax);
            am = fmaf(hm[i], Wsm[s * OUTD + lane * 8 + i], am);
        }
        for (int off = 16; off; off >>= 1) {
            ax += __shfl_xor_sync(0xFFFFFFFFu, ax, off);
            am += __shfl_xor_sync(0xFFFFFFFFu, am, off);
        }
        qx[s] = ax + bsx[s];
        qm[s] = am + bsm[s];
    }
    float num = 0.0f, nx = 0.0f, nm = 0.0f;
#pragma unroll
    for (int s = 0; s < 4; s++) {
        num = fmaf(qx[s], qm[s], num);
        nx = fmaf(qx[s], qx[s], nx);
        nm = fmaf(qm[s], qm[s], nm);
    }
    float den = fmaxf(sqrtf(nx), 1e-8f) * fmaxf(sqrtf(nm), 1e-8f);
    float g = 1.0f / (1.0f + expf(-num / den));
#pragma unroll
    for (int i = 0; i < 8; i++) {
        out[b * OUTD + lane * 8 + i] = g * hx[i] + (1.0f - g) * hm[i];
    }
}

// ---------------- launcher -------------------------------------------------
// Launch #4 = k_gemm_mma (ncu-profiled slot).
extern "C" void kernel_launch(void* const* d_in, const int* in_sizes, int n_in,
                              void* d_out, int out_size) {
    const float* x      = (const float*)d_in[0];
    const float* W_emb  = (const float*)d_in[1];
    const float* b_emb  = (const float*)d_in[2];
    const float* gamma  = (const float*)d_in[3];
    const float* beta   = (const float*)d_in[4];
    const float* memory = (const float*)d_in[5];
    const float* w_ih_x = (const float*)d_in[6];
    const float* w_hh_x = (const float*)d_in[7];
    const float* b_ih_x = (const float*)d_in[8];
    const float* b_hh_x = (const float*)d_in[9];
    const float* w_ih_m = (const float*)d_in[10];
    const float* w_hh_m = (const float*)d_in[11];
    const float* b_ih_m = (const float*)d_in[12];
    const float* b_hh_m = (const float*)d_in[13];
    const float* W_sx   = (const float*)d_in[14];
    const float* b_sx   = (const float*)d_in[15];
    const float* W_sm   = (const float*)d_in[16];
    const float* b_sm   = (const float*)d_in[17];
    float* out = (float*)d_out;

    const int smem_mma = 2 * 2 * BUFE * (int)sizeof(__nv_bfloat16);  // 73728 B
    static int attr_set = 0;
    if (!attr_set) {
        cudaFuncSetAttribute(k_gemm_mma, cudaFuncAttributeMaxDynamicSharedMemorySize,
                             smem_mma);
        attr_set = 1;
    }

    // 1: prep (zero stats + whh interleaved re-layout + gim)
    k_prep<<<897, 256>>>(w_hh_x, w_hh_m, memory, w_ih_m, b_ih_m);
    // 2: embed GEMM + leaky + BN stats + fused finalize
    k_embed<<<dim3(256, 8), 256>>>(x, W_emb, b_emb, gamma, beta);
    // 3: bf16 hi/lo split of BN(e) and w_ih_x
    k_convert<<<16768, 256>>>(w_ih_x);
    // 4: HMMA gi GEMM  (ncu-profiled slot)
    k_gemm_mma<<<dim3(256, 6), 128, smem_mma>>>(b_ih_x);
    // 5: recurrences
    k_scan<<<65, 384>>>(b_hh_x, b_hh_m);
    // 6: gate + blend
    k_final<<<256, 32>>>(W_sx, b_sx, W_sm, b_sm, out);
}